// round 13
// baseline (speedup 1.0000x reference)
#include <cuda_runtime.h>
#include <cuda_bf16.h>
#include <math.h>
#include <stdint.h>

#define NMAX 10000
#define EMAX 320000
#define HEADS 4
#define HID 128
#define QKV 512  // HEADS*HID

// ---------------- device scratch (static, no allocation) ----------------
__device__ float  g_Q[NMAX * QKV];
__device__ __nv_bfloat16 g_Kh[NMAX * QKV];
__device__ __nv_bfloat16 g_Vh[NMAX * QKV];
__device__ float  g_S[NMAX * HID];
__device__ float  g_H[NMAX * HID];
__device__ float4 g_W4[EMAX];          // per-edge exp weights (4 heads)
__device__ float  g_InvS[NMAX * HEADS];
__device__ int    g_deg[NMAX];
__device__ int    g_off[NMAX + 1];
__device__ int    g_cur[NMAX];
__device__ int    g_srcs[EMAX];
__device__ float  g_Wt[638976];        // transposed weights [Nc, K] packed

#define WT_Q0 0
#define WT_K0 131072
#define WT_V0 262144
#define WT_S0 393216
#define WT_Q1 425984
#define WT_K1 491520
#define WT_V1 557056
#define WT_S1 622592

__device__ __forceinline__ float2 bf2f2(uint32_t u) {
    __nv_bfloat162 h = *reinterpret_cast<__nv_bfloat162*>(&u);
    return __bfloat1622float2(h);
}

__device__ __forceinline__ uint32_t smem_u32(const void* p) {
    uint32_t a;
    asm("{ .reg .u64 t; cvta.to.shared.u64 t, %1; cvt.u32.u64 %0, t; }"
        : "=r"(a) : "l"(p));
    return a;
}

__device__ __forceinline__ void cp16(uint32_t s, const void* g) {
    asm volatile("cp.async.ca.shared.global [%0], [%1], 16;" :: "r"(s), "l"(g));
}
#define CP_COMMIT() asm volatile("cp.async.commit_group;" ::: "memory")
#define CP_WAIT1()  asm volatile("cp.async.wait_group 1;" ::: "memory")
#define CP_WAIT0()  asm volatile("cp.async.wait_group 0;" ::: "memory")

// ---------------- CSR build ----------------
__global__ void zero_int_kernel(int* p, int n) {
    int i = blockIdx.x * blockDim.x + threadIdx.x;
    if (i < n) p[i] = 0;
}

__global__ void count_deg_kernel(const int* __restrict__ dst, int* __restrict__ deg, int e) {
    int i = blockIdx.x * blockDim.x + threadIdx.x;
    if (i < e) atomicAdd(&deg[dst[i]], 1);
}

__global__ void scan_kernel(const int* __restrict__ deg, int* __restrict__ off,
                            int* __restrict__ cur, int n, int e) {
    __shared__ int part[1024];
    int t = threadIdx.x;
    int chunk = (n + 1023) / 1024;
    int lo = t * chunk;
    int hi = lo + chunk; if (hi > n) hi = n;
    int s = 0;
    for (int i = lo; i < hi; i++) s += deg[i];
    part[t] = s;
    __syncthreads();
    for (int d = 1; d < 1024; d <<= 1) {
        int v = (t >= d) ? part[t - d] : 0;
        __syncthreads();
        part[t] += v;
        __syncthreads();
    }
    int run = part[t] - s;
    for (int i = lo; i < hi; i++) {
        off[i] = run;
        cur[i] = run;
        run += deg[i];
    }
    if (t == 0) off[n] = e;
}

__global__ void scatter_kernel(const int* __restrict__ ei, int* __restrict__ cur,
                               int* __restrict__ srcs, int e) {
    int i = blockIdx.x * blockDim.x + threadIdx.x;
    if (i < e) {
        int s = ei[i];
        int d = ei[e + i];
        int p = atomicAdd(&cur[d], 1);
        srcs[p] = s;
    }
}

// ---------------- weight transpose: Wt[n][k] = W[k][n], z selects matrix -----
__global__ void transpose3_kernel(const float* __restrict__ W0, const float* __restrict__ W1,
                                  const float* __restrict__ W2,
                                  float* __restrict__ T0, float* __restrict__ T1,
                                  float* __restrict__ T2, int K, int Nc) {
    const float* W = (blockIdx.z == 0) ? W0 : (blockIdx.z == 1) ? W1 : W2;
    float* Wt      = (blockIdx.z == 0) ? T0 : (blockIdx.z == 1) ? T1 : T2;
    __shared__ float t[32][33];
    int x = blockIdx.x * 32 + threadIdx.x;
    int y = blockIdx.y * 32 + threadIdx.y;
#pragma unroll
    for (int i = 0; i < 32; i += 8)
        if (y + i < K && x < Nc) t[threadIdx.y + i][threadIdx.x] = W[(size_t)(y + i) * Nc + x];
    __syncthreads();
    x = blockIdx.y * 32 + threadIdx.x;
    y = blockIdx.x * 32 + threadIdx.y;
#pragma unroll
    for (int i = 0; i < 32; i += 8)
        if (y + i < Nc && x < K) Wt[(size_t)(y + i) * K + x] = t[threadIdx.x][threadIdx.y + i];
}

// ---------------- tf32 mma.sync GEMM, cp.async double-buffered ----------------
#define TM 128
#define TN 128
#define TBK 16
#define SSTRIDE 20

__device__ __forceinline__ uint32_t f2tf32(float f) {
    uint32_t r;
    asm("cvt.rna.tf32.f32 %0, %1;" : "=r"(r) : "f"(f));
    return r;
}

__device__ __forceinline__ void mma_tf32(float c[4], const uint32_t a[4],
                                         const uint32_t b[2]) {
    asm volatile(
        "mma.sync.aligned.m16n8k8.row.col.f32.tf32.tf32.f32 "
        "{%0,%1,%2,%3}, {%4,%5,%6,%7}, {%8,%9}, {%0,%1,%2,%3};"
        : "+f"(c[0]), "+f"(c[1]), "+f"(c[2]), "+f"(c[3])
        : "r"(a[0]), "r"(a[1]), "r"(a[2]), "r"(a[3]), "r"(b[0]), "r"(b[1]));
}

__global__ __launch_bounds__(256) void tf32_gemm_kernel(
    const float* __restrict__ A,
    const float* __restrict__ Wt0, const float* __restrict__ Wt1, const float* __restrict__ Wt2,
    const float* __restrict__ b0_, const float* __restrict__ b1_, const float* __restrict__ b2_,
    float* __restrict__ C0, float* __restrict__ C1, float* __restrict__ C2,
    __nv_bfloat16* __restrict__ Ch1, __nv_bfloat16* __restrict__ Ch2,
    int M, int K, int Nc)
{
    const float* Wt   = (blockIdx.z == 0) ? Wt0 : (blockIdx.z == 1) ? Wt1 : Wt2;
    const float* bias = (blockIdx.z == 0) ? b0_ : (blockIdx.z == 1) ? b1_ : b2_;
    float*       C    = (blockIdx.z == 0) ? C0  : (blockIdx.z == 1) ? C1  : C2;
    __nv_bfloat16* Ch = (blockIdx.z == 1) ? Ch1 : (blockIdx.z == 2) ? Ch2 : (__nv_bfloat16*)0;

    __shared__ float sA[2][TM * SSTRIDE];
    __shared__ float sB[2][TN * SSTRIDE];

    const int tid  = threadIdx.x;
    const int wid  = tid >> 5;
    const int lane = tid & 31;
    const int bm = blockIdx.y * TM;
    const int bn = blockIdx.x * TN;

    const int warp_m = wid >> 2;
    const int warp_n = wid & 3;
    const int m0w = warp_m * 64;
    const int n0w = warp_n * 32;
    const int grp = lane >> 2;
    const int tig = lane & 3;

    const int lr = (tid * 2) >> 2;
    const int lc0 = (tid * 2) & 3;
    const int lr1 = (tid * 2 + 1) >> 2;
    const int lc1 = (tid * 2 + 1) & 3;
    int arow0 = bm + lr;  if (arow0 >= M) arow0 = M - 1;
    int arow1 = bm + lr1; if (arow1 >= M) arow1 = M - 1;
    const uint32_t saA = smem_u32(&sA[0][0]);
    const uint32_t saB = smem_u32(&sB[0][0]);
    const uint32_t bufStride = TM * SSTRIDE * 4;

    float acc[4][4][4];
#pragma unroll
    for (int mt = 0; mt < 4; mt++)
#pragma unroll
        for (int nt = 0; nt < 4; nt++)
#pragma unroll
            for (int i = 0; i < 4; i++) acc[mt][nt][i] = 0.f;

    const int ktiles = K / TBK;

#define LOAD_TILE(KT, BUF)                                                          \
    do {                                                                            \
        const int k0_ = (KT) * TBK;                                                 \
        cp16(saA + (BUF) * bufStride + (lr * SSTRIDE + lc0 * 4) * 4,                \
             &A[(size_t)arow0 * K + k0_ + lc0 * 4]);                                \
        cp16(saA + (BUF) * bufStride + (lr1 * SSTRIDE + lc1 * 4) * 4,               \
             &A[(size_t)arow1 * K + k0_ + lc1 * 4]);                                \
        cp16(saB + (BUF) * bufStride + (lr * SSTRIDE + lc0 * 4) * 4,                \
             &Wt[(size_t)(bn + lr) * K + k0_ + lc0 * 4]);                           \
        cp16(saB + (BUF) * bufStride + (lr1 * SSTRIDE + lc1 * 4) * 4,               \
             &Wt[(size_t)(bn + lr1) * K + k0_ + lc1 * 4]);                          \
    } while (0)

    LOAD_TILE(0, 0);
    CP_COMMIT();

    for (int kt = 0; kt < ktiles; kt++) {
        if (kt + 1 < ktiles) {
            LOAD_TILE(kt + 1, (kt + 1) & 1);
            CP_COMMIT();
            CP_WAIT1();
        } else {
            CP_WAIT0();
        }
        __syncthreads();

        const float* Ab = &sA[kt & 1][0];
        const float* Bb = &sB[kt & 1][0];
#pragma unroll
        for (int ks = 0; ks < 2; ks++) {
            uint32_t af[4][4], bf[4][2];
#pragma unroll
            for (int mt = 0; mt < 4; mt++) {
                int base = (m0w + mt * 16 + grp) * SSTRIDE + ks * 8 + tig;
                af[mt][0] = f2tf32(Ab[base]);
                af[mt][1] = f2tf32(Ab[base + 8 * SSTRIDE]);
                af[mt][2] = f2tf32(Ab[base + 4]);
                af[mt][3] = f2tf32(Ab[base + 8 * SSTRIDE + 4]);
            }
#pragma unroll
            for (int nt = 0; nt < 4; nt++) {
                int base = (n0w + nt * 8 + grp) * SSTRIDE + ks * 8 + tig;
                bf[nt][0] = f2tf32(Bb[base]);
                bf[nt][1] = f2tf32(Bb[base + 4]);
            }
#pragma unroll
            for (int mt = 0; mt < 4; mt++)
#pragma unroll
                for (int nt = 0; nt < 4; nt++)
                    mma_tf32(acc[mt][nt], af[mt], bf[nt]);
        }
        __syncthreads();
    }

#pragma unroll
    for (int mt = 0; mt < 4; mt++) {
        int r0 = bm + m0w + mt * 16 + grp;
        int r1 = r0 + 8;
#pragma unroll
        for (int nt = 0; nt < 4; nt++) {
            int col = bn + n0w + nt * 8 + 2 * tig;
            float2 bi = *(const float2*)&bias[col];
            float vx0 = acc[mt][nt][0] + bi.x, vy0 = acc[mt][nt][1] + bi.y;
            float vx1 = acc[mt][nt][2] + bi.x, vy1 = acc[mt][nt][3] + bi.y;
            if (Ch) {
                if (r0 < M) {
                    __nv_bfloat162 h = __floats2bfloat162_rn(vx0, vy0);
                    *(__nv_bfloat162*)&Ch[(size_t)r0 * Nc + col] = h;
                }
                if (r1 < M) {
                    __nv_bfloat162 h = __floats2bfloat162_rn(vx1, vy1);
                    *(__nv_bfloat162*)&Ch[(size_t)r1 * Nc + col] = h;
                }
            } else {
                if (r0 < M) *(float2*)&C[(size_t)r0 * Nc + col] = make_float2(vx0, vy0);
                if (r1 < M) *(float2*)&C[(size_t)r1 * Nc + col] = make_float2(vx1, vy1);
            }
        }
    }
}

// ---------------- attention pass 1: logits (bf16 K), 8 warps/node ----------
__global__ __launch_bounds__(256) void attn_pass1_kernel(
    const float* __restrict__ Q, const __nv_bfloat16* __restrict__ Kh,
    const int* __restrict__ off, const int* __restrict__ srcs,
    float4* __restrict__ Wbuf, float* __restrict__ InvS)
{
    int node = blockIdx.x;
    int tid = threadIdx.x;
    int lane = tid & 31;
    int w = tid >> 5;                      // 0..7

    __shared__ float wmax[8][4];
    __shared__ float wsum[8][4];
    __shared__ float m_s[4];

    const float scale = 0.08838834764831845f;  // 1/sqrt(128)
    float qreg[16];
    {
        const float4* qg = (const float4*)(Q + (size_t)node * QKV);
#pragma unroll
        for (int c = 0; c < 4; c++) {
            float4 v = qg[lane * 4 + c];
            qreg[c * 4 + 0] = v.x * scale;
            qreg[c * 4 + 1] = v.y * scale;
            qreg[c * 4 + 2] = v.z * scale;
            qreg[c * 4 + 3] = v.w * scale;
        }
    }

    int start = off[node], end = off[node + 1];

    float lmax[4] = {-1e30f, -1e30f, -1e30f, -1e30f};
    // software-pipelined: prefetch edge j+8 while computing j (static registers)
    uint4 k0N, k1N;
    {
        int j0 = start + w;
        if (j0 < end) {
            const uint4* kg = (const uint4*)(Kh + (size_t)srcs[j0] * QKV);
            k0N = kg[lane * 2];
            k1N = kg[lane * 2 + 1];
        }
    }
    for (int j = start + w; j < end; j += 8) {
        uint4 k0 = k0N, k1 = k1N;
        if (j + 8 < end) {
            const uint4* kg = (const uint4*)(Kh + (size_t)srcs[j + 8] * QKV);
            k0N = kg[lane * 2];
            k1N = kg[lane * 2 + 1];
        }
        float part = 0.f;
        {
            float2 a;
            a = bf2f2(k0.x); part += qreg[0] * a.x + qreg[1] * a.y;
            a = bf2f2(k0.y); part += qreg[2] * a.x + qreg[3] * a.y;
            a = bf2f2(k0.z); part += qreg[4] * a.x + qreg[5] * a.y;
            a = bf2f2(k0.w); part += qreg[6] * a.x + qreg[7] * a.y;
            a = bf2f2(k1.x); part += qreg[8] * a.x + qreg[9] * a.y;
            a = bf2f2(k1.y); part += qreg[10] * a.x + qreg[11] * a.y;
            a = bf2f2(k1.z); part += qreg[12] * a.x + qreg[13] * a.y;
            a = bf2f2(k1.w); part += qreg[14] * a.x + qreg[15] * a.y;
        }
        part += __shfl_xor_sync(0xFFFFFFFFu, part, 1);
        part += __shfl_xor_sync(0xFFFFFFFFu, part, 2);
        part += __shfl_xor_sync(0xFFFFFFFFu, part, 4);
        float d0 = __shfl_sync(0xFFFFFFFFu, part, 0);
        float d1 = __shfl_sync(0xFFFFFFFFu, part, 8);
        float d2 = __shfl_sync(0xFFFFFFFFu, part, 16);
        float d3 = __shfl_sync(0xFFFFFFFFu, part, 24);
        if (lane == 0) {
            Wbuf[j] = make_float4(d0, d1, d2, d3);
            lmax[0] = fmaxf(lmax[0], d0);
            lmax[1] = fmaxf(lmax[1], d1);
            lmax[2] = fmaxf(lmax[2], d2);
            lmax[3] = fmaxf(lmax[3], d3);
        }
    }
    if (lane == 0) {
        wmax[w][0] = lmax[0]; wmax[w][1] = lmax[1];
        wmax[w][2] = lmax[2]; wmax[w][3] = lmax[3];
    }
    __syncthreads();
    if (tid < 4) {
        float m = wmax[0][tid];
#pragma unroll
        for (int ww = 1; ww < 8; ww++) m = fmaxf(m, wmax[ww][tid]);
        m_s[tid] = m;
    }
    __syncthreads();
    float m0 = m_s[0], m1 = m_s[1], m2 = m_s[2], m3 = m_s[3];

    float p0 = 0.f, p1 = 0.f, p2 = 0.f, p3 = 0.f;
    for (int j = start + tid; j < end; j += 256) {
        float4 a = Wbuf[j];
        a.x = __expf(a.x - m0);
        a.y = __expf(a.y - m1);
        a.z = __expf(a.z - m2);
        a.w = __expf(a.w - m3);
        Wbuf[j] = a;
        p0 += a.x; p1 += a.y; p2 += a.z; p3 += a.w;
    }
#pragma unroll
    for (int o = 16; o > 0; o >>= 1) {
        p0 += __shfl_xor_sync(0xFFFFFFFFu, p0, o);
        p1 += __shfl_xor_sync(0xFFFFFFFFu, p1, o);
        p2 += __shfl_xor_sync(0xFFFFFFFFu, p2, o);
        p3 += __shfl_xor_sync(0xFFFFFFFFu, p3, o);
    }
    if (lane == 0) {
        wsum[w][0] = p0; wsum[w][1] = p1; wsum[w][2] = p2; wsum[w][3] = p3;
    }
    __syncthreads();
    if (tid < 4) {
        float s = 0.f;
#pragma unroll
        for (int ww = 0; ww < 8; ww++) s += wsum[ww][tid];
        InvS[node * HEADS + tid] = 0.25f / (s + 1e-16f);
    }
}

// ---------------- attention pass 2: weighted V sum, 2 groups x unroll 8 ------
__global__ __launch_bounds__(256) void attn_pass2_kernel(
    const __nv_bfloat16* __restrict__ Vh, const float4* __restrict__ Wbuf,
    const float* __restrict__ InvS, const float* __restrict__ S,
    const int* __restrict__ off, const int* __restrict__ srcs,
    float* __restrict__ Out)
{
    int node = blockIdx.x;
    int tid = threadIdx.x;
    int g = tid >> 7;                 // 0 or 1 : edge-range group
    int ltid = tid & 127;             // position within group
    int head = ltid >> 5;
    __shared__ float sm[1024];

    int start = off[node], end = off[node + 1];
    int mid = start + ((end - start) >> 1);
    int lo = g ? mid : start;
    int hi = g ? end : mid;

    float4 acc = make_float4(0.f, 0.f, 0.f, 0.f);
    int j = lo;
    for (; j + 7 < hi; j += 8) {
        int s0 = srcs[j],     s1 = srcs[j + 1], s2 = srcs[j + 2], s3 = srcs[j + 3];
        int s4 = srcs[j + 4], s5 = srcs[j + 5], s6 = srcs[j + 6], s7 = srcs[j + 7];
        uint2 u0 = ((const uint2*)(Vh + (size_t)s0 * QKV))[ltid];
        uint2 u1 = ((const uint2*)(Vh + (size_t)s1 * QKV))[ltid];
        uint2 u2 = ((const uint2*)(Vh + (size_t)s2 * QKV))[ltid];
        uint2 u3 = ((const uint2*)(Vh + (size_t)s3 * QKV))[ltid];
        uint2 u4 = ((const uint2*)(Vh + (size_t)s4 * QKV))[ltid];
        uint2 u5 = ((const uint2*)(Vh + (size_t)s5 * QKV))[ltid];
        uint2 u6 = ((const uint2*)(Vh + (size_t)s6 * QKV))[ltid];
        uint2 u7 = ((const uint2*)(Vh + (size_t)s7 * QKV))[ltid];
        float4 w0 = Wbuf[j],     w1 = Wbuf[j + 1], w2 = Wbuf[j + 2], w3 = Wbuf[j + 3];
        float4 w4 = Wbuf[j + 4], w5 = Wbuf[j + 5], w6 = Wbuf[j + 6], w7 = Wbuf[j + 7];
        float g0 = (head == 0) ? w0.x : (head == 1) ? w0.y : (head == 2) ? w0.z : w0.w;
        float g1 = (head == 0) ? w1.x : (head == 1) ? w1.y : (head == 2) ? w1.z : w1.w;
        float g2 = (head == 0) ? w2.x : (head == 1) ? w2.y : (head == 2) ? w2.z : w2.w;
        float g3 = (head == 0) ? w3.x : (head == 1) ? w3.y : (head == 2) ? w3.z : w3.w;
        float g4 = (head == 0) ? w4.x : (head == 1) ? w4.y : (head == 2) ? w4.z : w4.w;
        float g5 = (head == 0) ? w5.x : (head == 1) ? w5.y : (head == 2) ? w5.z : w5.w;
        float g6 = (head == 0) ? w6.x : (head == 1) ? w6.y : (head == 2) ? w6.z : w6.w;
        float g7 = (head == 0) ? w7.x : (head == 1) ? w7.y : (head == 2) ? w7.z : w7.w;
        float2 a0 = bf2f2(u0.x), b0 = bf2f2(u0.y);
        float2 a1 = bf2f2(u1.x), b1 = bf2f2(u1.y);
        float2 a2 = bf2f2(u2.x), b2 = bf2f2(u2.y);
        float2 a3 = bf2f2(u3.x), b3 = bf2f2(u3.y);
        float2 a4 = bf2f2(u4.x), b4 = bf2f2(u4.y);
        float2 a5 = bf2f2(u5.x), b5 = bf2f2(u5.y);
        float2 a6 = bf2f2(u6.x), b6 = bf2f2(u6.y);
        float2 a7 = bf2f2(u7.x), b7 = bf2f2(u7.y);
        acc.x += g0 * a0.x + g1 * a1.x + g2 * a2.x + g3 * a3.x
               + g4 * a4.x + g5 * a5.x + g6 * a6.x + g7 * a7.x;
        acc.y += g0 * a0.y + g1 * a1.y + g2 * a2.y + g3 * a3.y
               + g4 * a4.y + g5 * a5.y + g6 * a6.y + g7 * a7.y;
        acc.z += g0 * b0.x + g1 * b1.x + g2 * b2.x + g3 * b3.x
               + g4 * b4.x + g5 * b5.x + g6 * b6.x + g7 * b7.x;
        acc.w += g0 * b0.y + g1 * b1.y + g2 * b2.y + g3 * b3.y
               + g4 * b4.y + g5 * b5.y + g6 * b6.y + g7 * b7.y;
    }
    for (; j < hi; j++) {
        int s0 = srcs[j];
        uint2 u0 = ((const uint2*)(Vh + (size_t)s0 * QKV))[ltid];
        float4 w0 = Wbuf[j];
        float g0 = (head == 0) ? w0.x : (head == 1) ? w0.y : (head == 2) ? w0.z : w0.w;
        float2 a0 = bf2f2(u0.x), b0 = bf2f2(u0.y);
        acc.x += g0 * a0.x;
        acc.y += g0 * a0.y;
        acc.z += g0 * b0.x;
        acc.w += g0 * b0.y;
    }
    float inv = InvS[node * HEADS + head];
    acc.x *= inv; acc.y *= inv; acc.z *= inv; acc.w *= inv;
    *(float4*)&sm[tid * 4] = acc;
    __syncthreads();

    if (tid < 32) {
#pragma unroll
        for (int i = 0; i < 4; i++) {
            int c = tid * 4 + i;
            float s = sm[c] + sm[128 + c] + sm[256 + c] + sm[384 + c]
                    + sm[512 + c] + sm[640 + c] + sm[768 + c] + sm[896 + c]
                    + S[(size_t)node * HID + c];
            Out[(size_t)node * HID + c] = fmaxf(s, 0.f);
        }
    }
}

// ---------------- launch ----------------
extern "C" void kernel_launch(void* const* d_in, const int* in_sizes, int n_in,
                              void* d_out, int out_size) {
    const float* x   = (const float*)d_in[0];
    const int*   ei  = (const int*)d_in[1];
    const float* Wq0 = (const float*)d_in[3],  *bq0 = (const float*)d_in[4];
    const float* Wk0 = (const float*)d_in[5],  *bk0 = (const float*)d_in[6];
    const float* Wv0 = (const float*)d_in[7],  *bv0 = (const float*)d_in[8];
    const float* Ws0 = (const float*)d_in[9],  *bs0 = (const float*)d_in[10];
    const float* Wq1 = (const float*)d_in[11], *bq1 = (const float*)d_in[12];
    const float* Wk1 = (const float*)d_in[13], *bk1 = (const float*)d_in[14];
    const float* Wv1 = (const float*)d_in[15], *bv1 = (const float*)d_in[16];
    const float* Ws1 = (const float*)d_in[17], *bs1 = (const float*)d_in[18];
    float* out = (float*)d_out;

    int n = in_sizes[0] / 256;
    int e = in_sizes[1] / 2;

    float *Q, *S, *H, *InvS, *Wt;
    __nv_bfloat16 *Kh, *Vh;
    float4* W4;
    int *deg, *off, *cur, *srcs;
    cudaGetSymbolAddress((void**)&Q,    g_Q);
    cudaGetSymbolAddress((void**)&Kh,   g_Kh);
    cudaGetSymbolAddress((void**)&Vh,   g_Vh);
    cudaGetSymbolAddress((void**)&S,    g_S);
    cudaGetSymbolAddress((void**)&H,    g_H);
    cudaGetSymbolAddress((void**)&InvS, g_InvS);
    cudaGetSymbolAddress((void**)&W4,   g_W4);
    cudaGetSymbolAddress((void**)&deg,  g_deg);
    cudaGetSymbolAddress((void**)&off,  g_off);
    cudaGetSymbolAddress((void**)&cur,  g_cur);
    cudaGetSymbolAddress((void**)&srcs, g_srcs);
    cudaGetSymbolAddress((void**)&Wt,   g_Wt);

    int tb = 256;
    // ---- CSR build ----
    zero_int_kernel<<<(n + tb - 1) / tb, tb>>>(deg, n);
    count_deg_kernel<<<(e + tb - 1) / tb, tb>>>(ei + e, deg, e);
    scan_kernel<<<1, 1024>>>(deg, off, cur, n, e);
    scatter_kernel<<<(e + tb - 1) / tb, tb>>>(ei, cur, srcs, e);

    // ---- weight transposes (4 launches) ----
    dim3 tpb(32, 8);
    {
        dim3 g0(QKV / 32, 256 / 32, 3);
        dim3 gs0(HID / 32, 256 / 32, 1);
        dim3 g1(QKV / 32, 128 / 32, 3);
        dim3 gs1(HID / 32, 128 / 32, 1);
        transpose3_kernel<<<g0, tpb>>>(Wq0, Wk0, Wv0,
                                       Wt + WT_Q0, Wt + WT_K0, Wt + WT_V0, 256, QKV);
        transpose3_kernel<<<gs0, tpb>>>(Ws0, Ws0, Ws0,
                                        Wt + WT_S0, Wt + WT_S0, Wt + WT_S0, 256, HID);
        transpose3_kernel<<<g1, tpb>>>(Wq1, Wk1, Wv1,
                                       Wt + WT_Q1, Wt + WT_K1, Wt + WT_V1, 128, QKV);
        transpose3_kernel<<<gs1, tpb>>>(Ws1, Ws1, Ws1,
                                        Wt + WT_S1, Wt + WT_S1, Wt + WT_S1, 128, HID);
    }

    const int gy = (n + TM - 1) / TM;

    // ---- layer 0 (d_in = 256) ----
    {
        dim3 gqkv(QKV / TN, gy, 3);
        dim3 gs(HID / TN, gy, 1);
        tf32_gemm_kernel<<<gqkv, 256>>>(x, Wt + WT_Q0, Wt + WT_K0, Wt + WT_V0,
                                        bq0, bk0, bv0, Q, Q, Q, Kh, Vh, n, 256, QKV);
        tf32_gemm_kernel<<<gs, 256>>>(x, Wt + WT_S0, Wt + WT_S0, Wt + WT_S0,
                                      bs0, bs0, bs0, S, S, S,
                                      (__nv_bfloat16*)0, (__nv_bfloat16*)0, n, 256, HID);
        attn_pass1_kernel<<<n, 256>>>(Q, Kh, off, srcs, W4, InvS);
        attn_pass2_kernel<<<n, 256>>>(Vh, W4, InvS, S, off, srcs, H);
    }
    // ---- layer 1 (d_in = 128) ----
    {
        dim3 gqkv(QKV / TN, gy, 3);
        dim3 gs(HID / TN, gy, 1);
        tf32_gemm_kernel<<<gqkv, 256>>>(H, Wt + WT_Q1, Wt + WT_K1, Wt + WT_V1,
                                        bq1, bk1, bv1, Q, Q, Q, Kh, Vh, n, 128, QKV);
        tf32_gemm_kernel<<<gs, 256>>>(H, Wt + WT_S1, Wt + WT_S1, Wt + WT_S1,
                                      bs1, bs1, bs1, S, S, S,
                                      (__nv_bfloat16*)0, (__nv_bfloat16*)0, n, 128, HID);
        attn_pass1_kernel<<<n, 256>>>(Q, Kh, off, srcs, W4, InvS);
        attn_pass2_kernel<<<n, 256>>>(Vh, W4, InvS, S, off, srcs, out);
    }
}

// round 14
// speedup vs baseline: 1.1572x; 1.1572x over previous
#include <cuda_runtime.h>
#include <cuda_bf16.h>
#include <math.h>
#include <stdint.h>

#define NMAX 10000
#define EMAX 320000
#define HEADS 4
#define HID 128
#define QKV 512  // HEADS*HID
#define ECAP 1024 // smem logit tile capacity (edges)

// ---------------- device scratch (static, no allocation) ----------------
__device__ float  g_Q[NMAX * QKV];
__device__ __nv_bfloat16 g_Kh[NMAX * QKV];
__device__ __nv_bfloat16 g_Vh[NMAX * QKV];
__device__ float  g_S[NMAX * HID];
__device__ float  g_H[NMAX * HID];
__device__ int    g_deg[NMAX];
__device__ int    g_off[NMAX + 1];
__device__ int    g_cur[NMAX];
__device__ int    g_srcs[EMAX];
__device__ float  g_Wt[638976];        // transposed weights [Nc, K] packed

#define WT_Q0 0
#define WT_K0 131072
#define WT_V0 262144
#define WT_S0 393216
#define WT_Q1 425984
#define WT_K1 491520
#define WT_V1 557056
#define WT_S1 622592

__device__ __forceinline__ float2 bf2f2(uint32_t u) {
    __nv_bfloat162 h = *reinterpret_cast<__nv_bfloat162*>(&u);
    return __bfloat1622float2(h);
}

__device__ __forceinline__ uint32_t smem_u32(const void* p) {
    uint32_t a;
    asm("{ .reg .u64 t; cvta.to.shared.u64 t, %1; cvt.u32.u64 %0, t; }"
        : "=r"(a) : "l"(p));
    return a;
}

__device__ __forceinline__ void cp16(uint32_t s, const void* g) {
    asm volatile("cp.async.ca.shared.global [%0], [%1], 16;" :: "r"(s), "l"(g));
}
#define CP_COMMIT() asm volatile("cp.async.commit_group;" ::: "memory")
#define CP_WAIT1()  asm volatile("cp.async.wait_group 1;" ::: "memory")
#define CP_WAIT0()  asm volatile("cp.async.wait_group 0;" ::: "memory")

// ---------------- CSR build ----------------
__global__ void zero_int_kernel(int* p, int n) {
    int i = blockIdx.x * blockDim.x + threadIdx.x;
    if (i < n) p[i] = 0;
}

__global__ void count_deg_kernel(const int* __restrict__ dst, int* __restrict__ deg, int e) {
    int i = blockIdx.x * blockDim.x + threadIdx.x;
    if (i < e) atomicAdd(&deg[dst[i]], 1);
}

__global__ void scan_kernel(const int* __restrict__ deg, int* __restrict__ off,
                            int* __restrict__ cur, int n, int e) {
    __shared__ int part[1024];
    int t = threadIdx.x;
    int chunk = (n + 1023) / 1024;
    int lo = t * chunk;
    int hi = lo + chunk; if (hi > n) hi = n;
    int s = 0;
    for (int i = lo; i < hi; i++) s += deg[i];
    part[t] = s;
    __syncthreads();
    for (int d = 1; d < 1024; d <<= 1) {
        int v = (t >= d) ? part[t - d] : 0;
        __syncthreads();
        part[t] += v;
        __syncthreads();
    }
    int run = part[t] - s;
    for (int i = lo; i < hi; i++) {
        off[i] = run;
        cur[i] = run;
        run += deg[i];
    }
    if (t == 0) off[n] = e;
}

__global__ void scatter_kernel(const int* __restrict__ ei, int* __restrict__ cur,
                               int* __restrict__ srcs, int e) {
    int i = blockIdx.x * blockDim.x + threadIdx.x;
    if (i < e) {
        int s = ei[i];
        int d = ei[e + i];
        int p = atomicAdd(&cur[d], 1);
        srcs[p] = s;
    }
}

// ---------------- weight transpose: Wt[n][k] = W[k][n], z selects matrix -----
__global__ void transpose3_kernel(const float* __restrict__ W0, const float* __restrict__ W1,
                                  const float* __restrict__ W2,
                                  float* __restrict__ T0, float* __restrict__ T1,
                                  float* __restrict__ T2, int K, int Nc) {
    const float* W = (blockIdx.z == 0) ? W0 : (blockIdx.z == 1) ? W1 : W2;
    float* Wt      = (blockIdx.z == 0) ? T0 : (blockIdx.z == 1) ? T1 : T2;
    __shared__ float t[32][33];
    int x = blockIdx.x * 32 + threadIdx.x;
    int y = blockIdx.y * 32 + threadIdx.y;
#pragma unroll
    for (int i = 0; i < 32; i += 8)
        if (y + i < K && x < Nc) t[threadIdx.y + i][threadIdx.x] = W[(size_t)(y + i) * Nc + x];
    __syncthreads();
    x = blockIdx.y * 32 + threadIdx.x;
    y = blockIdx.x * 32 + threadIdx.y;
#pragma unroll
    for (int i = 0; i < 32; i += 8)
        if (y + i < Nc && x < K) Wt[(size_t)(y + i) * K + x] = t[threadIdx.x][threadIdx.y + i];
}

// ---------------- tf32 mma.sync GEMM, cp.async double-buffered ----------------
#define TM 128
#define TN 128
#define TBK 16
#define SSTRIDE 20

__device__ __forceinline__ uint32_t f2tf32(float f) {
    uint32_t r;
    asm("cvt.rna.tf32.f32 %0, %1;" : "=r"(r) : "f"(f));
    return r;
}

__device__ __forceinline__ void mma_tf32(float c[4], const uint32_t a[4],
                                         const uint32_t b[2]) {
    asm volatile(
        "mma.sync.aligned.m16n8k8.row.col.f32.tf32.tf32.f32 "
        "{%0,%1,%2,%3}, {%4,%5,%6,%7}, {%8,%9}, {%0,%1,%2,%3};"
        : "+f"(c[0]), "+f"(c[1]), "+f"(c[2]), "+f"(c[3])
        : "r"(a[0]), "r"(a[1]), "r"(a[2]), "r"(a[3]), "r"(b[0]), "r"(b[1]));
}

__global__ __launch_bounds__(256) void tf32_gemm_kernel(
    const float* __restrict__ A,
    const float* __restrict__ Wt0, const float* __restrict__ Wt1, const float* __restrict__ Wt2,
    const float* __restrict__ b0_, const float* __restrict__ b1_, const float* __restrict__ b2_,
    float* __restrict__ C0, float* __restrict__ C1, float* __restrict__ C2,
    __nv_bfloat16* __restrict__ Ch1, __nv_bfloat16* __restrict__ Ch2,
    int M, int K, int Nc)
{
    const float* Wt   = (blockIdx.z == 0) ? Wt0 : (blockIdx.z == 1) ? Wt1 : Wt2;
    const float* bias = (blockIdx.z == 0) ? b0_ : (blockIdx.z == 1) ? b1_ : b2_;
    float*       C    = (blockIdx.z == 0) ? C0  : (blockIdx.z == 1) ? C1  : C2;
    __nv_bfloat16* Ch = (blockIdx.z == 1) ? Ch1 : (blockIdx.z == 2) ? Ch2 : (__nv_bfloat16*)0;

    __shared__ float sA[2][TM * SSTRIDE];
    __shared__ float sB[2][TN * SSTRIDE];

    const int tid  = threadIdx.x;
    const int wid  = tid >> 5;
    const int lane = tid & 31;
    const int bm = blockIdx.y * TM;
    const int bn = blockIdx.x * TN;

    const int warp_m = wid >> 2;
    const int warp_n = wid & 3;
    const int m0w = warp_m * 64;
    const int n0w = warp_n * 32;
    const int grp = lane >> 2;
    const int tig = lane & 3;

    const int lr = (tid * 2) >> 2;
    const int lc0 = (tid * 2) & 3;
    const int lr1 = (tid * 2 + 1) >> 2;
    const int lc1 = (tid * 2 + 1) & 3;
    int arow0 = bm + lr;  if (arow0 >= M) arow0 = M - 1;
    int arow1 = bm + lr1; if (arow1 >= M) arow1 = M - 1;
    const uint32_t saA = smem_u32(&sA[0][0]);
    const uint32_t saB = smem_u32(&sB[0][0]);
    const uint32_t bufStride = TM * SSTRIDE * 4;

    float acc[4][4][4];
#pragma unroll
    for (int mt = 0; mt < 4; mt++)
#pragma unroll
        for (int nt = 0; nt < 4; nt++)
#pragma unroll
            for (int i = 0; i < 4; i++) acc[mt][nt][i] = 0.f;

    const int ktiles = K / TBK;

#define LOAD_TILE(KT, BUF)                                                          \
    do {                                                                            \
        const int k0_ = (KT) * TBK;                                                 \
        cp16(saA + (BUF) * bufStride + (lr * SSTRIDE + lc0 * 4) * 4,                \
             &A[(size_t)arow0 * K + k0_ + lc0 * 4]);                                \
        cp16(saA + (BUF) * bufStride + (lr1 * SSTRIDE + lc1 * 4) * 4,               \
             &A[(size_t)arow1 * K + k0_ + lc1 * 4]);                                \
        cp16(saB + (BUF) * bufStride + (lr * SSTRIDE + lc0 * 4) * 4,                \
             &Wt[(size_t)(bn + lr) * K + k0_ + lc0 * 4]);                           \
        cp16(saB + (BUF) * bufStride + (lr1 * SSTRIDE + lc1 * 4) * 4,               \
             &Wt[(size_t)(bn + lr1) * K + k0_ + lc1 * 4]);                          \
    } while (0)

    LOAD_TILE(0, 0);
    CP_COMMIT();

    for (int kt = 0; kt < ktiles; kt++) {
        if (kt + 1 < ktiles) {
            LOAD_TILE(kt + 1, (kt + 1) & 1);
            CP_COMMIT();
            CP_WAIT1();
        } else {
            CP_WAIT0();
        }
        __syncthreads();

        const float* Ab = &sA[kt & 1][0];
        const float* Bb = &sB[kt & 1][0];
#pragma unroll
        for (int ks = 0; ks < 2; ks++) {
            uint32_t af[4][4], bf[4][2];
#pragma unroll
            for (int mt = 0; mt < 4; mt++) {
                int base = (m0w + mt * 16 + grp) * SSTRIDE + ks * 8 + tig;
                af[mt][0] = f2tf32(Ab[base]);
                af[mt][1] = f2tf32(Ab[base + 8 * SSTRIDE]);
                af[mt][2] = f2tf32(Ab[base + 4]);
                af[mt][3] = f2tf32(Ab[base + 8 * SSTRIDE + 4]);
            }
#pragma unroll
            for (int nt = 0; nt < 4; nt++) {
                int base = (n0w + nt * 8 + grp) * SSTRIDE + ks * 8 + tig;
                bf[nt][0] = f2tf32(Bb[base]);
                bf[nt][1] = f2tf32(Bb[base + 4]);
            }
#pragma unroll
            for (int mt = 0; mt < 4; mt++)
#pragma unroll
                for (int nt = 0; nt < 4; nt++)
                    mma_tf32(acc[mt][nt], af[mt], bf[nt]);
        }
        __syncthreads();
    }

#pragma unroll
    for (int mt = 0; mt < 4; mt++) {
        int r0 = bm + m0w + mt * 16 + grp;
        int r1 = r0 + 8;
#pragma unroll
        for (int nt = 0; nt < 4; nt++) {
            int col = bn + n0w + nt * 8 + 2 * tig;
            float2 bi = *(const float2*)&bias[col];
            float vx0 = acc[mt][nt][0] + bi.x, vy0 = acc[mt][nt][1] + bi.y;
            float vx1 = acc[mt][nt][2] + bi.x, vy1 = acc[mt][nt][3] + bi.y;
            if (Ch) {
                if (r0 < M) {
                    __nv_bfloat162 h = __floats2bfloat162_rn(vx0, vy0);
                    *(__nv_bfloat162*)&Ch[(size_t)r0 * Nc + col] = h;
                }
                if (r1 < M) {
                    __nv_bfloat162 h = __floats2bfloat162_rn(vx1, vy1);
                    *(__nv_bfloat162*)&Ch[(size_t)r1 * Nc + col] = h;
                }
            } else {
                if (r0 < M) *(float2*)&C[(size_t)r0 * Nc + col] = make_float2(vx0, vy0);
                if (r1 < M) *(float2*)&C[(size_t)r1 * Nc + col] = make_float2(vx1, vy1);
            }
        }
    }
}

// ---------------- fused attention: smem logits, two-phase per tile -----------
// 128 threads. Phase A = R12 pass1 structure (warp-per-edge logits -> smem).
// Phase B = R12 pass2 structure (unroll-8 V gather, weights from smem).
// Tiles of ECAP edges with flash-style rescale for arbitrary degree
// (actual max degree ~60 -> single tile, rescale factors are exp(0)=1 or 0).
__global__ __launch_bounds__(128) void attn_fused_kernel(
    const float* __restrict__ Q, const __nv_bfloat16* __restrict__ Kh,
    const __nv_bfloat16* __restrict__ Vh, const float* __restrict__ S,
    const int* __restrict__ off, const int* __restrict__ srcs,
    float* __restrict__ Out)
{
    int node = blockIdx.x;
    int tid = threadIdx.x;
    int lane = tid & 31;
    int w = tid >> 5;
    int head = tid >> 5;

    __shared__ float4 sw[ECAP];       // logits -> exp weights
    __shared__ float wred[4][4];
    __shared__ float rm_s[4];         // running max per head
    __shared__ float nm_s[4];         // new max per head
    __shared__ float cs_s[4];         // rescale factor per head
    __shared__ float ts_s[4];         // tile sum per head
    __shared__ float outsm[512];

    const float scale = 0.08838834764831845f;  // 1/sqrt(128)
    float qreg[16];
    {
        const float4* qg = (const float4*)(Q + (size_t)node * QKV);
#pragma unroll
        for (int c = 0; c < 4; c++) {
            float4 v = qg[lane * 4 + c];
            qreg[c * 4 + 0] = v.x * scale;
            qreg[c * 4 + 1] = v.y * scale;
            qreg[c * 4 + 2] = v.z * scale;
            qreg[c * 4 + 3] = v.w * scale;
        }
    }

    if (tid < 4) rm_s[tid] = -1e30f;

    int start = off[node], end = off[node + 1];

    float s_run = 0.f;                       // per-head (this thread's head)
    float4 acc = make_float4(0.f, 0.f, 0.f, 0.f);

    for (int t0 = start; t0 < end; t0 += ECAP) {
        int t1 = t0 + ECAP; if (t1 > end) t1 = end;
        int tn = t1 - t0;
        __syncthreads();  // sw reusable (also covers rm_s init on first iter)

        // ---- Phase A: logits into smem (R12 pass1 loop, prefetch dist 4) ----
        {
            uint4 k0N, k1N;
            int j0 = t0 + w;
            if (j0 < t1) {
                const uint4* kg = (const uint4*)(Kh + (size_t)srcs[j0] * QKV);
                k0N = kg[lane * 2];
                k1N = kg[lane * 2 + 1];
            }
            for (int j = t0 + w; j < t1; j += 4) {
                uint4 k0 = k0N, k1 = k1N;
                if (j + 4 < t1) {
                    const uint4* kg = (const uint4*)(Kh + (size_t)srcs[j + 4] * QKV);
                    k0N = kg[lane * 2];
                    k1N = kg[lane * 2 + 1];
                }
                float part = 0.f;
                {
                    float2 a;
                    a = bf2f2(k0.x); part += qreg[0] * a.x + qreg[1] * a.y;
                    a = bf2f2(k0.y); part += qreg[2] * a.x + qreg[3] * a.y;
                    a = bf2f2(k0.z); part += qreg[4] * a.x + qreg[5] * a.y;
                    a = bf2f2(k0.w); part += qreg[6] * a.x + qreg[7] * a.y;
                    a = bf2f2(k1.x); part += qreg[8] * a.x + qreg[9] * a.y;
                    a = bf2f2(k1.y); part += qreg[10] * a.x + qreg[11] * a.y;
                    a = bf2f2(k1.z); part += qreg[12] * a.x + qreg[13] * a.y;
                    a = bf2f2(k1.w); part += qreg[14] * a.x + qreg[15] * a.y;
                }
                part += __shfl_xor_sync(0xFFFFFFFFu, part, 1);
                part += __shfl_xor_sync(0xFFFFFFFFu, part, 2);
                part += __shfl_xor_sync(0xFFFFFFFFu, part, 4);
                float d0 = __shfl_sync(0xFFFFFFFFu, part, 0);
                float d1 = __shfl_sync(0xFFFFFFFFu, part, 8);
                float d2 = __shfl_sync(0xFFFFFFFFu, part, 16);
                float d3 = __shfl_sync(0xFFFFFFFFu, part, 24);
                if (lane == 0) sw[j - t0] = make_float4(d0, d1, d2, d3);
            }
        }
        __syncthreads();

        // ---- tile max per head ----
        {
            float t0m = -1e30f, t1m = -1e30f, t2m = -1e30f, t3m = -1e30f;
            for (int i = tid; i < tn; i += 128) {
                float4 a = sw[i];
                t0m = fmaxf(t0m, a.x); t1m = fmaxf(t1m, a.y);
                t2m = fmaxf(t2m, a.z); t3m = fmaxf(t3m, a.w);
            }
#pragma unroll
            for (int o = 16; o > 0; o >>= 1) {
                t0m = fmaxf(t0m, __shfl_xor_sync(0xFFFFFFFFu, t0m, o));
                t1m = fmaxf(t1m, __shfl_xor_sync(0xFFFFFFFFu, t1m, o));
                t2m = fmaxf(t2m, __shfl_xor_sync(0xFFFFFFFFu, t2m, o));
                t3m = fmaxf(t3m, __shfl_xor_sync(0xFFFFFFFFu, t3m, o));
            }
            if (lane == 0) {
                wred[w][0] = t0m; wred[w][1] = t1m;
                wred[w][2] = t2m; wred[w][3] = t3m;
            }
        }
        __syncthreads();
        if (tid < 4) {
            float tm = fmaxf(fmaxf(wred[0][tid], wred[1][tid]),
                             fmaxf(wred[2][tid], wred[3][tid]));
            float old = rm_s[tid];
            float nm = fmaxf(old, tm);
            nm_s[tid] = nm;
            cs_s[tid] = __expf(old - nm);
            rm_s[tid] = nm;
        }
        __syncthreads();
        float m0 = nm_s[0], m1 = nm_s[1], m2 = nm_s[2], m3 = nm_s[3];

        // ---- exp conversion + tile sum ----
        {
            float p0 = 0.f, p1 = 0.f, p2 = 0.f, p3 = 0.f;
            for (int i = tid; i < tn; i += 128) {
                float4 a = sw[i];
                a.x = __expf(a.x - m0);
                a.y = __expf(a.y - m1);
                a.z = __expf(a.z - m2);
                a.w = __expf(a.w - m3);
                sw[i] = a;
                p0 += a.x; p1 += a.y; p2 += a.z; p3 += a.w;
            }
#pragma unroll
            for (int o = 16; o > 0; o >>= 1) {
                p0 += __shfl_xor_sync(0xFFFFFFFFu, p0, o);
                p1 += __shfl_xor_sync(0xFFFFFFFFu, p1, o);
                p2 += __shfl_xor_sync(0xFFFFFFFFu, p2, o);
                p3 += __shfl_xor_sync(0xFFFFFFFFu, p3, o);
            }
            if (lane == 0) {
                wred[w][0] = p0; wred[w][1] = p1;
                wred[w][2] = p2; wred[w][3] = p3;
            }
        }
        __syncthreads();
        if (tid < 4)
            ts_s[tid] = wred[0][tid] + wred[1][tid] + wred[2][tid] + wred[3][tid];
        __syncthreads();

        // rescale running accumulators (per thread; head fixed)
        {
            float cs = cs_s[head];
            s_run = s_run * cs + ts_s[head];
            acc.x *= cs; acc.y *= cs; acc.z *= cs; acc.w *= cs;
        }

        // ---- Phase B: V gather, unroll 8, weights from smem ----
        const float* swf = (const float*)sw;
        int j = t0;
        for (; j + 7 < t1; j += 8) {
            int b = j - t0;
            int s0 = srcs[j],     s1 = srcs[j + 1], s2 = srcs[j + 2], s3 = srcs[j + 3];
            int s4 = srcs[j + 4], s5 = srcs[j + 5], s6 = srcs[j + 6], s7 = srcs[j + 7];
            uint2 u0 = ((const uint2*)(Vh + (size_t)s0 * QKV))[tid];
            uint2 u1 = ((const uint2*)(Vh + (size_t)s1 * QKV))[tid];
            uint2 u2 = ((const uint2*)(Vh + (size_t)s2 * QKV))[tid];
            uint2 u3 = ((const uint2*)(Vh + (size_t)s3 * QKV))[tid];
            uint2 u4 = ((const uint2*)(Vh + (size_t)s4 * QKV))[tid];
            uint2 u5 = ((const uint2*)(Vh + (size_t)s5 * QKV))[tid];
            uint2 u6 = ((const uint2*)(Vh + (size_t)s6 * QKV))[tid];
            uint2 u7 = ((const uint2*)(Vh + (size_t)s7 * QKV))[tid];
            float g0 = swf[(b + 0) * 4 + head];
            float g1 = swf[(b + 1) * 4 + head];
            float g2 = swf[(b + 2) * 4 + head];
            float g3 = swf[(b + 3) * 4 + head];
            float g4 = swf[(b + 4) * 4 + head];
            float g5 = swf[(b + 5) * 4 + head];
            float g6 = swf[(b + 6) * 4 + head];
            float g7 = swf[(b + 7) * 4 + head];
            float2 a0 = bf2f2(u0.x), b0 = bf2f2(u0.y);
            float2 a1 = bf2f2(u1.x), b1 = bf2f2(u1.y);
            float2 a2 = bf2f2(u2.x), b2 = bf2f2(u2.y);
            float2 a3 = bf2f2(u3.x), b3 = bf2f2(u3.y);
            float2 a4 = bf2f2(u4.x), b4 = bf2f2(u4.y);
            float2 a5 = bf2f2(u5.x), b5 = bf2f2(u5.y);
            float2 a6 = bf2f2(u6.x), b6 = bf2f2(u6.y);
            float2 a7 = bf2f2(u7.x), b7 = bf2f2(u7.y);
            acc.x += g0 * a0.x + g1 * a1.x + g2 * a2.x + g3 * a3.x
                   + g4 * a4.x + g5 * a5.x + g6 * a6.x + g7 * a7.x;
            acc.y += g0 * a0.y + g1 * a1.y + g2 * a2.y + g3 * a3.y
                   + g4 * a4.y + g5 * a5.y + g6 * a6.y + g7 * a7.y;
            acc.z += g0 * b0.x + g1 * b1.x + g2 * b2.x + g3 * b3.x
                   + g4 * b4.x + g5 * b5.x + g6 * b6.x + g7 * b7.x;
            acc.w += g0 * b0.y + g1 * b1.y + g2 * b2.y + g3 * b3.y
                   + g4 * b4.y + g5 * b5.y + g6 * b6.y + g7 * b7.y;
        }
        for (; j < t1; j++) {
            int s0 = srcs[j];
            uint2 u0 = ((const uint2*)(Vh + (size_t)s0 * QKV))[tid];
            float g0 = swf[(j - t0) * 4 + head];
            float2 a0 = bf2f2(u0.x), b0 = bf2f2(u0.y);
            acc.x += g0 * a0.x;
            acc.y += g0 * a0.y;
            acc.z += g0 * b0.x;
            acc.w += g0 * b0.y;
        }
    }

    float inv = 0.25f / (s_run + 1e-16f);   // head-mean folded in
    acc.x *= inv; acc.y *= inv; acc.z *= inv; acc.w *= inv;
    __syncthreads();
    *(float4*)&outsm[tid * 4] = acc;
    __syncthreads();

    if (tid < 32) {
#pragma unroll
        for (int i = 0; i < 4; i++) {
            int c = tid * 4 + i;
            float s = outsm[c] + outsm[128 + c] + outsm[256 + c] + outsm[384 + c]
                    + S[(size_t)node * HID + c];
            Out[(size_t)node * HID + c] = fmaxf(s, 0.f);
        }
    }
}

// ---------------- launch ----------------
extern "C" void kernel_launch(void* const* d_in, const int* in_sizes, int n_in,
                              void* d_out, int out_size) {
    const float* x   = (const float*)d_in[0];
    const int*   ei  = (const int*)d_in[1];
    const float* Wq0 = (const float*)d_in[3],  *bq0 = (const float*)d_in[4];
    const float* Wk0 = (const float*)d_in[5],  *bk0 = (const float*)d_in[6];
    const float* Wv0 = (const float*)d_in[7],  *bv0 = (const float*)d_in[8];
    const float* Ws0 = (const float*)d_in[9],  *bs0 = (const float*)d_in[10];
    const float* Wq1 = (const float*)d_in[11], *bq1 = (const float*)d_in[12];
    const float* Wk1 = (const float*)d_in[13], *bk1 = (const float*)d_in[14];
    const float* Wv1 = (const float*)d_in[15], *bv1 = (const float*)d_in[16];
    const float* Ws1 = (const float*)d_in[17], *bs1 = (const float*)d_in[18];
    float* out = (float*)d_out;

    int n = in_sizes[0] / 256;
    int e = in_sizes[1] / 2;

    float *Q, *S, *H, *Wt;
    __nv_bfloat16 *Kh, *Vh;
    int *deg, *off, *cur, *srcs;
    cudaGetSymbolAddress((void**)&Q,    g_Q);
    cudaGetSymbolAddress((void**)&Kh,   g_Kh);
    cudaGetSymbolAddress((void**)&Vh,   g_Vh);
    cudaGetSymbolAddress((void**)&S,    g_S);
    cudaGetSymbolAddress((void**)&H,    g_H);
    cudaGetSymbolAddress((void**)&deg,  g_deg);
    cudaGetSymbolAddress((void**)&off,  g_off);
    cudaGetSymbolAddress((void**)&cur,  g_cur);
    cudaGetSymbolAddress((void**)&srcs, g_srcs);
    cudaGetSymbolAddress((void**)&Wt,   g_Wt);

    int tb = 256;
    // ---- CSR build ----
    zero_int_kernel<<<(n + tb - 1) / tb, tb>>>(deg, n);
    count_deg_kernel<<<(e + tb - 1) / tb, tb>>>(ei + e, deg, e);
    scan_kernel<<<1, 1024>>>(deg, off, cur, n, e);
    scatter_kernel<<<(e + tb - 1) / tb, tb>>>(ei, cur, srcs, e);

    // ---- weight transposes (4 launches) ----
    dim3 tpb(32, 8);
    {
        dim3 g0(QKV / 32, 256 / 32, 3);
        dim3 gs0(HID / 32, 256 / 32, 1);
        dim3 g1(QKV / 32, 128 / 32, 3);
        dim3 gs1(HID / 32, 128 / 32, 1);
        transpose3_kernel<<<g0, tpb>>>(Wq0, Wk0, Wv0,
                                       Wt + WT_Q0, Wt + WT_K0, Wt + WT_V0, 256, QKV);
        transpose3_kernel<<<gs0, tpb>>>(Ws0, Ws0, Ws0,
                                        Wt + WT_S0, Wt + WT_S0, Wt + WT_S0, 256, HID);
        transpose3_kernel<<<g1, tpb>>>(Wq1, Wk1, Wv1,
                                       Wt + WT_Q1, Wt + WT_K1, Wt + WT_V1, 128, QKV);
        transpose3_kernel<<<gs1, tpb>>>(Ws1, Ws1, Ws1,
                                        Wt + WT_S1, Wt + WT_S1, Wt + WT_S1, 128, HID);
    }

    const int gy = (n + TM - 1) / TM;

    // ---- layer 0 (d_in = 256) ----
    {
        dim3 gqkv(QKV / TN, gy, 3);
        dim3 gs(HID / TN, gy, 1);
        tf32_gemm_kernel<<<gqkv, 256>>>(x, Wt + WT_Q0, Wt + WT_K0, Wt + WT_V0,
                                        bq0, bk0, bv0, Q, Q, Q, Kh, Vh, n, 256, QKV);
        tf32_gemm_kernel<<<gs, 256>>>(x, Wt + WT_S0, Wt + WT_S0, Wt + WT_S0,
                                      bs0, bs0, bs0, S, S, S,
                                      (__nv_bfloat16*)0, (__nv_bfloat16*)0, n, 256, HID);
        attn_fused_kernel<<<n, 128>>>(Q, Kh, Vh, S, off, srcs, H);
    }
    // ---- layer 1 (d_in = 128) ----
    {
        dim3 gqkv(QKV / TN, gy, 3);
        dim3 gs(HID / TN, gy, 1);
        tf32_gemm_kernel<<<gqkv, 256>>>(H, Wt + WT_Q1, Wt + WT_K1, Wt + WT_V1,
                                        bq1, bk1, bv1, Q, Q, Q, Kh, Vh, n, 128, QKV);
        tf32_gemm_kernel<<<gs, 256>>>(H, Wt + WT_S1, Wt + WT_S1, Wt + WT_S1,
                                      bs1, bs1, bs1, S, S, S,
                                      (__nv_bfloat16*)0, (__nv_bfloat16*)0, n, 128, HID);
        attn_fused_kernel<<<n, 128>>>(Q, Kh, Vh, S, off, srcs, out);
    }
}

// round 15
// speedup vs baseline: 1.2210x; 1.0551x over previous
#include <cuda_runtime.h>
#include <cuda_bf16.h>
#include <math.h>
#include <stdint.h>

#define NMAX 10000
#define EMAX 320000
#define HEADS 4
#define HID 128
#define QKV 512  // HEADS*HID
#define ECAP 1024 // smem logit tile capacity (edges)

// ---------------- device scratch (static, no allocation) ----------------
__device__ float  g_Q[NMAX * QKV];
__device__ __nv_bfloat16 g_Kh[NMAX * QKV];
__device__ __nv_bfloat16 g_Vh[NMAX * QKV];
__device__ float  g_S[NMAX * HID];
__device__ float  g_H[NMAX * HID];
__device__ int    g_deg[NMAX];
__device__ int    g_off[NMAX + 1];
__device__ int    g_cur[NMAX];
__device__ int    g_srcs[EMAX];
__device__ float  g_Wt[638976];        // transposed weights [Nc, K] packed

#define WT_Q0 0
#define WT_K0 131072
#define WT_V0 262144
#define WT_S0 393216
#define WT_Q1 425984
#define WT_K1 491520
#define WT_V1 557056
#define WT_S1 622592

__device__ __forceinline__ float2 bf2f2(uint32_t u) {
    __nv_bfloat162 h = *reinterpret_cast<__nv_bfloat162*>(&u);
    return __bfloat1622float2(h);
}

__device__ __forceinline__ uint32_t smem_u32(const void* p) {
    uint32_t a;
    asm("{ .reg .u64 t; cvta.to.shared.u64 t, %1; cvt.u32.u64 %0, t; }"
        : "=r"(a) : "l"(p));
    return a;
}

__device__ __forceinline__ void cp16(uint32_t s, const void* g) {
    asm volatile("cp.async.ca.shared.global [%0], [%1], 16;" :: "r"(s), "l"(g));
}
#define CP_COMMIT() asm volatile("cp.async.commit_group;" ::: "memory")
#define CP_WAIT1()  asm volatile("cp.async.wait_group 1;" ::: "memory")
#define CP_WAIT0()  asm volatile("cp.async.wait_group 0;" ::: "memory")

// ---------------- CSR build ----------------
__global__ void zero_int_kernel(int* p, int n) {
    int i = blockIdx.x * blockDim.x + threadIdx.x;
    if (i < n) p[i] = 0;
}

__global__ void count_deg_kernel(const int* __restrict__ dst, int* __restrict__ deg, int e) {
    int i = blockIdx.x * blockDim.x + threadIdx.x;
    if (i < e) atomicAdd(&deg[dst[i]], 1);
}

__global__ void scan_kernel(const int* __restrict__ deg, int* __restrict__ off,
                            int* __restrict__ cur, int n, int e) {
    __shared__ int part[1024];
    int t = threadIdx.x;
    int chunk = (n + 1023) / 1024;
    int lo = t * chunk;
    int hi = lo + chunk; if (hi > n) hi = n;
    int s = 0;
    for (int i = lo; i < hi; i++) s += deg[i];
    part[t] = s;
    __syncthreads();
    for (int d = 1; d < 1024; d <<= 1) {
        int v = (t >= d) ? part[t - d] : 0;
        __syncthreads();
        part[t] += v;
        __syncthreads();
    }
    int run = part[t] - s;
    for (int i = lo; i < hi; i++) {
        off[i] = run;
        cur[i] = run;
        run += deg[i];
    }
    if (t == 0) off[n] = e;
}

__global__ void scatter_kernel(const int* __restrict__ ei, int* __restrict__ cur,
                               int* __restrict__ srcs, int e) {
    int i = blockIdx.x * blockDim.x + threadIdx.x;
    if (i < e) {
        int s = ei[i];
        int d = ei[e + i];
        int p = atomicAdd(&cur[d], 1);
        srcs[p] = s;
    }
}

// ---------------- weight transpose: Wt[n][k] = W[k][n], z selects matrix -----
__global__ void transpose3_kernel(const float* __restrict__ W0, const float* __restrict__ W1,
                                  const float* __restrict__ W2,
                                  float* __restrict__ T0, float* __restrict__ T1,
                                  float* __restrict__ T2, int K, int Nc) {
    const float* W = (blockIdx.z == 0) ? W0 : (blockIdx.z == 1) ? W1 : W2;
    float* Wt      = (blockIdx.z == 0) ? T0 : (blockIdx.z == 1) ? T1 : T2;
    __shared__ float t[32][33];
    int x = blockIdx.x * 32 + threadIdx.x;
    int y = blockIdx.y * 32 + threadIdx.y;
#pragma unroll
    for (int i = 0; i < 32; i += 8)
        if (y + i < K && x < Nc) t[threadIdx.y + i][threadIdx.x] = W[(size_t)(y + i) * Nc + x];
    __syncthreads();
    x = blockIdx.y * 32 + threadIdx.x;
    y = blockIdx.x * 32 + threadIdx.y;
#pragma unroll
    for (int i = 0; i < 32; i += 8)
        if (y + i < Nc && x < K) Wt[(size_t)(y + i) * K + x] = t[threadIdx.x][threadIdx.y + i];
}

// ---------------- tf32 mma.sync GEMM, cp.async double-buffered ----------------
#define TM 128
#define TN 128
#define TBK 16
#define SSTRIDE 20

__device__ __forceinline__ uint32_t f2tf32(float f) {
    uint32_t r;
    asm("cvt.rna.tf32.f32 %0, %1;" : "=r"(r) : "f"(f));
    return r;
}

__device__ __forceinline__ void mma_tf32(float c[4], const uint32_t a[4],
                                         const uint32_t b[2]) {
    asm volatile(
        "mma.sync.aligned.m16n8k8.row.col.f32.tf32.tf32.f32 "
        "{%0,%1,%2,%3}, {%4,%5,%6,%7}, {%8,%9}, {%0,%1,%2,%3};"
        : "+f"(c[0]), "+f"(c[1]), "+f"(c[2]), "+f"(c[3])
        : "r"(a[0]), "r"(a[1]), "r"(a[2]), "r"(a[3]), "r"(b[0]), "r"(b[1]));
}

__global__ __launch_bounds__(256) void tf32_gemm_kernel(
    const float* __restrict__ A,
    const float* __restrict__ Wt0, const float* __restrict__ Wt1, const float* __restrict__ Wt2,
    const float* __restrict__ b0_, const float* __restrict__ b1_, const float* __restrict__ b2_,
    float* __restrict__ C0, float* __restrict__ C1, float* __restrict__ C2,
    __nv_bfloat16* __restrict__ Ch1, __nv_bfloat16* __restrict__ Ch2,
    int M, int K, int Nc)
{
    const float* Wt   = (blockIdx.z == 0) ? Wt0 : (blockIdx.z == 1) ? Wt1 : Wt2;
    const float* bias = (blockIdx.z == 0) ? b0_ : (blockIdx.z == 1) ? b1_ : b2_;
    float*       C    = (blockIdx.z == 0) ? C0  : (blockIdx.z == 1) ? C1  : C2;
    __nv_bfloat16* Ch = (blockIdx.z == 1) ? Ch1 : (blockIdx.z == 2) ? Ch2 : (__nv_bfloat16*)0;

    __shared__ float sA[2][TM * SSTRIDE];
    __shared__ float sB[2][TN * SSTRIDE];

    const int tid  = threadIdx.x;
    const int wid  = tid >> 5;
    const int lane = tid & 31;
    const int bm = blockIdx.y * TM;
    const int bn = blockIdx.x * TN;

    const int warp_m = wid >> 2;
    const int warp_n = wid & 3;
    const int m0w = warp_m * 64;
    const int n0w = warp_n * 32;
    const int grp = lane >> 2;
    const int tig = lane & 3;

    const int lr = (tid * 2) >> 2;
    const int lc0 = (tid * 2) & 3;
    const int lr1 = (tid * 2 + 1) >> 2;
    const int lc1 = (tid * 2 + 1) & 3;
    int arow0 = bm + lr;  if (arow0 >= M) arow0 = M - 1;
    int arow1 = bm + lr1; if (arow1 >= M) arow1 = M - 1;
    const uint32_t saA = smem_u32(&sA[0][0]);
    const uint32_t saB = smem_u32(&sB[0][0]);
    const uint32_t bufStride = TM * SSTRIDE * 4;

    float acc[4][4][4];
#pragma unroll
    for (int mt = 0; mt < 4; mt++)
#pragma unroll
        for (int nt = 0; nt < 4; nt++)
#pragma unroll
            for (int i = 0; i < 4; i++) acc[mt][nt][i] = 0.f;

    const int ktiles = K / TBK;

#define LOAD_TILE(KT, BUF)                                                          \
    do {                                                                            \
        const int k0_ = (KT) * TBK;                                                 \
        cp16(saA + (BUF) * bufStride + (lr * SSTRIDE + lc0 * 4) * 4,                \
             &A[(size_t)arow0 * K + k0_ + lc0 * 4]);                                \
        cp16(saA + (BUF) * bufStride + (lr1 * SSTRIDE + lc1 * 4) * 4,               \
             &A[(size_t)arow1 * K + k0_ + lc1 * 4]);                                \
        cp16(saB + (BUF) * bufStride + (lr * SSTRIDE + lc0 * 4) * 4,                \
             &Wt[(size_t)(bn + lr) * K + k0_ + lc0 * 4]);                           \
        cp16(saB + (BUF) * bufStride + (lr1 * SSTRIDE + lc1 * 4) * 4,               \
             &Wt[(size_t)(bn + lr1) * K + k0_ + lc1 * 4]);                          \
    } while (0)

    LOAD_TILE(0, 0);
    CP_COMMIT();

    for (int kt = 0; kt < ktiles; kt++) {
        if (kt + 1 < ktiles) {
            LOAD_TILE(kt + 1, (kt + 1) & 1);
            CP_COMMIT();
            CP_WAIT1();
        } else {
            CP_WAIT0();
        }
        __syncthreads();

        const float* Ab = &sA[kt & 1][0];
        const float* Bb = &sB[kt & 1][0];
#pragma unroll
        for (int ks = 0; ks < 2; ks++) {
            uint32_t af[4][4], bf[4][2];
#pragma unroll
            for (int mt = 0; mt < 4; mt++) {
                int base = (m0w + mt * 16 + grp) * SSTRIDE + ks * 8 + tig;
                af[mt][0] = f2tf32(Ab[base]);
                af[mt][1] = f2tf32(Ab[base + 8 * SSTRIDE]);
                af[mt][2] = f2tf32(Ab[base + 4]);
                af[mt][3] = f2tf32(Ab[base + 8 * SSTRIDE + 4]);
            }
#pragma unroll
            for (int nt = 0; nt < 4; nt++) {
                int base = (n0w + nt * 8 + grp) * SSTRIDE + ks * 8 + tig;
                bf[nt][0] = f2tf32(Bb[base]);
                bf[nt][1] = f2tf32(Bb[base + 4]);
            }
#pragma unroll
            for (int mt = 0; mt < 4; mt++)
#pragma unroll
                for (int nt = 0; nt < 4; nt++)
                    mma_tf32(acc[mt][nt], af[mt], bf[nt]);
        }
        __syncthreads();
    }

#pragma unroll
    for (int mt = 0; mt < 4; mt++) {
        int r0 = bm + m0w + mt * 16 + grp;
        int r1 = r0 + 8;
#pragma unroll
        for (int nt = 0; nt < 4; nt++) {
            int col = bn + n0w + nt * 8 + 2 * tig;
            float2 bi = *(const float2*)&bias[col];
            float vx0 = acc[mt][nt][0] + bi.x, vy0 = acc[mt][nt][1] + bi.y;
            float vx1 = acc[mt][nt][2] + bi.x, vy1 = acc[mt][nt][3] + bi.y;
            if (Ch) {
                if (r0 < M) {
                    __nv_bfloat162 h = __floats2bfloat162_rn(vx0, vy0);
                    *(__nv_bfloat162*)&Ch[(size_t)r0 * Nc + col] = h;
                }
                if (r1 < M) {
                    __nv_bfloat162 h = __floats2bfloat162_rn(vx1, vy1);
                    *(__nv_bfloat162*)&Ch[(size_t)r1 * Nc + col] = h;
                }
            } else {
                if (r0 < M) *(float2*)&C[(size_t)r0 * Nc + col] = make_float2(vx0, vy0);
                if (r1 < M) *(float2*)&C[(size_t)r1 * Nc + col] = make_float2(vx1, vy1);
            }
        }
    }
}

// ---------------- fused attention: smem logits, two-phase per tile -----------
__global__ __launch_bounds__(128) void attn_fused_kernel(
    const float* __restrict__ Q, const __nv_bfloat16* __restrict__ Kh,
    const __nv_bfloat16* __restrict__ Vh, const float* __restrict__ S,
    const int* __restrict__ off, const int* __restrict__ srcs,
    float* __restrict__ Out)
{
    int node = blockIdx.x;
    int tid = threadIdx.x;
    int lane = tid & 31;
    int w = tid >> 5;
    int head = tid >> 5;

    __shared__ float4 sw[ECAP];
    __shared__ float wred[4][4];
    __shared__ float rm_s[4];
    __shared__ float nm_s[4];
    __shared__ float cs_s[4];
    __shared__ float ts_s[4];
    __shared__ float outsm[512];

    const float scale = 0.08838834764831845f;  // 1/sqrt(128)
    float qreg[16];
    {
        const float4* qg = (const float4*)(Q + (size_t)node * QKV);
#pragma unroll
        for (int c = 0; c < 4; c++) {
            float4 v = qg[lane * 4 + c];
            qreg[c * 4 + 0] = v.x * scale;
            qreg[c * 4 + 1] = v.y * scale;
            qreg[c * 4 + 2] = v.z * scale;
            qreg[c * 4 + 3] = v.w * scale;
        }
    }

    if (tid < 4) rm_s[tid] = -1e30f;

    int start = off[node], end = off[node + 1];

    float s_run = 0.f;
    float4 acc = make_float4(0.f, 0.f, 0.f, 0.f);

    for (int t0 = start; t0 < end; t0 += ECAP) {
        int t1 = t0 + ECAP; if (t1 > end) t1 = end;
        int tn = t1 - t0;
        __syncthreads();

        // ---- Phase A: logits into smem ----
        {
            uint4 k0N, k1N;
            int j0 = t0 + w;
            if (j0 < t1) {
                const uint4* kg = (const uint4*)(Kh + (size_t)srcs[j0] * QKV);
                k0N = kg[lane * 2];
                k1N = kg[lane * 2 + 1];
            }
            for (int j = t0 + w; j < t1; j += 4) {
                uint4 k0 = k0N, k1 = k1N;
                if (j + 4 < t1) {
                    const uint4* kg = (const uint4*)(Kh + (size_t)srcs[j + 4] * QKV);
                    k0N = kg[lane * 2];
                    k1N = kg[lane * 2 + 1];
                }
                float part = 0.f;
                {
                    float2 a;
                    a = bf2f2(k0.x); part += qreg[0] * a.x + qreg[1] * a.y;
                    a = bf2f2(k0.y); part += qreg[2] * a.x + qreg[3] * a.y;
                    a = bf2f2(k0.z); part += qreg[4] * a.x + qreg[5] * a.y;
                    a = bf2f2(k0.w); part += qreg[6] * a.x + qreg[7] * a.y;
                    a = bf2f2(k1.x); part += qreg[8] * a.x + qreg[9] * a.y;
                    a = bf2f2(k1.y); part += qreg[10] * a.x + qreg[11] * a.y;
                    a = bf2f2(k1.z); part += qreg[12] * a.x + qreg[13] * a.y;
                    a = bf2f2(k1.w); part += qreg[14] * a.x + qreg[15] * a.y;
                }
                part += __shfl_xor_sync(0xFFFFFFFFu, part, 1);
                part += __shfl_xor_sync(0xFFFFFFFFu, part, 2);
                part += __shfl_xor_sync(0xFFFFFFFFu, part, 4);
                float d0 = __shfl_sync(0xFFFFFFFFu, part, 0);
                float d1 = __shfl_sync(0xFFFFFFFFu, part, 8);
                float d2 = __shfl_sync(0xFFFFFFFFu, part, 16);
                float d3 = __shfl_sync(0xFFFFFFFFu, part, 24);
                if (lane == 0) sw[j - t0] = make_float4(d0, d1, d2, d3);
            }
        }
        __syncthreads();

        // ---- tile max per head ----
        {
            float t0m = -1e30f, t1m = -1e30f, t2m = -1e30f, t3m = -1e30f;
            for (int i = tid; i < tn; i += 128) {
                float4 a = sw[i];
                t0m = fmaxf(t0m, a.x); t1m = fmaxf(t1m, a.y);
                t2m = fmaxf(t2m, a.z); t3m = fmaxf(t3m, a.w);
            }
#pragma unroll
            for (int o = 16; o > 0; o >>= 1) {
                t0m = fmaxf(t0m, __shfl_xor_sync(0xFFFFFFFFu, t0m, o));
                t1m = fmaxf(t1m, __shfl_xor_sync(0xFFFFFFFFu, t1m, o));
                t2m = fmaxf(t2m, __shfl_xor_sync(0xFFFFFFFFu, t2m, o));
                t3m = fmaxf(t3m, __shfl_xor_sync(0xFFFFFFFFu, t3m, o));
            }
            if (lane == 0) {
                wred[w][0] = t0m; wred[w][1] = t1m;
                wred[w][2] = t2m; wred[w][3] = t3m;
            }
        }
        __syncthreads();
        if (tid < 4) {
            float tm = fmaxf(fmaxf(wred[0][tid], wred[1][tid]),
                             fmaxf(wred[2][tid], wred[3][tid]));
            float old = rm_s[tid];
            float nm = fmaxf(old, tm);
            nm_s[tid] = nm;
            cs_s[tid] = __expf(old - nm);
            rm_s[tid] = nm;
        }
        __syncthreads();
        float m0 = nm_s[0], m1 = nm_s[1], m2 = nm_s[2], m3 = nm_s[3];

        // ---- exp conversion + tile sum ----
        {
            float p0 = 0.f, p1 = 0.f, p2 = 0.f, p3 = 0.f;
            for (int i = tid; i < tn; i += 128) {
                float4 a = sw[i];
                a.x = __expf(a.x - m0);
                a.y = __expf(a.y - m1);
                a.z = __expf(a.z - m2);
                a.w = __expf(a.w - m3);
                sw[i] = a;
                p0 += a.x; p1 += a.y; p2 += a.z; p3 += a.w;
            }
#pragma unroll
            for (int o = 16; o > 0; o >>= 1) {
                p0 += __shfl_xor_sync(0xFFFFFFFFu, p0, o);
                p1 += __shfl_xor_sync(0xFFFFFFFFu, p1, o);
                p2 += __shfl_xor_sync(0xFFFFFFFFu, p2, o);
                p3 += __shfl_xor_sync(0xFFFFFFFFu, p3, o);
            }
            if (lane == 0) {
                wred[w][0] = p0; wred[w][1] = p1;
                wred[w][2] = p2; wred[w][3] = p3;
            }
        }
        __syncthreads();
        if (tid < 4)
            ts_s[tid] = wred[0][tid] + wred[1][tid] + wred[2][tid] + wred[3][tid];
        __syncthreads();

        {
            float cs = cs_s[head];
            s_run = s_run * cs + ts_s[head];
            acc.x *= cs; acc.y *= cs; acc.z *= cs; acc.w *= cs;
        }

        // ---- Phase B: V gather, unroll 8, weights from smem ----
        const float* swf = (const float*)sw;
        int j = t0;
        for (; j + 7 < t1; j += 8) {
            int b = j - t0;
            int s0 = srcs[j],     s1 = srcs[j + 1], s2 = srcs[j + 2], s3 = srcs[j + 3];
            int s4 = srcs[j + 4], s5 = srcs[j + 5], s6 = srcs[j + 6], s7 = srcs[j + 7];
            uint2 u0 = ((const uint2*)(Vh + (size_t)s0 * QKV))[tid];
            uint2 u1 = ((const uint2*)(Vh + (size_t)s1 * QKV))[tid];
            uint2 u2 = ((const uint2*)(Vh + (size_t)s2 * QKV))[tid];
            uint2 u3 = ((const uint2*)(Vh + (size_t)s3 * QKV))[tid];
            uint2 u4 = ((const uint2*)(Vh + (size_t)s4 * QKV))[tid];
            uint2 u5 = ((const uint2*)(Vh + (size_t)s5 * QKV))[tid];
            uint2 u6 = ((const uint2*)(Vh + (size_t)s6 * QKV))[tid];
            uint2 u7 = ((const uint2*)(Vh + (size_t)s7 * QKV))[tid];
            float g0 = swf[(b + 0) * 4 + head];
            float g1 = swf[(b + 1) * 4 + head];
            float g2 = swf[(b + 2) * 4 + head];
            float g3 = swf[(b + 3) * 4 + head];
            float g4 = swf[(b + 4) * 4 + head];
            float g5 = swf[(b + 5) * 4 + head];
            float g6 = swf[(b + 6) * 4 + head];
            float g7 = swf[(b + 7) * 4 + head];
            float2 a0 = bf2f2(u0.x), b0 = bf2f2(u0.y);
            float2 a1 = bf2f2(u1.x), b1 = bf2f2(u1.y);
            float2 a2 = bf2f2(u2.x), b2 = bf2f2(u2.y);
            float2 a3 = bf2f2(u3.x), b3 = bf2f2(u3.y);
            float2 a4 = bf2f2(u4.x), b4 = bf2f2(u4.y);
            float2 a5 = bf2f2(u5.x), b5 = bf2f2(u5.y);
            float2 a6 = bf2f2(u6.x), b6 = bf2f2(u6.y);
            float2 a7 = bf2f2(u7.x), b7 = bf2f2(u7.y);
            acc.x += g0 * a0.x + g1 * a1.x + g2 * a2.x + g3 * a3.x
                   + g4 * a4.x + g5 * a5.x + g6 * a6.x + g7 * a7.x;
            acc.y += g0 * a0.y + g1 * a1.y + g2 * a2.y + g3 * a3.y
                   + g4 * a4.y + g5 * a5.y + g6 * a6.y + g7 * a7.y;
            acc.z += g0 * b0.x + g1 * b1.x + g2 * b2.x + g3 * b3.x
                   + g4 * b4.x + g5 * b5.x + g6 * b6.x + g7 * b7.x;
            acc.w += g0 * b0.y + g1 * b1.y + g2 * b2.y + g3 * b3.y
                   + g4 * b4.y + g5 * b5.y + g6 * b6.y + g7 * b7.y;
        }
        for (; j < t1; j++) {
            int s0 = srcs[j];
            uint2 u0 = ((const uint2*)(Vh + (size_t)s0 * QKV))[tid];
            float g0 = swf[(j - t0) * 4 + head];
            float2 a0 = bf2f2(u0.x), b0 = bf2f2(u0.y);
            acc.x += g0 * a0.x;
            acc.y += g0 * a0.y;
            acc.z += g0 * b0.x;
            acc.w += g0 * b0.y;
        }
    }

    float inv = 0.25f / (s_run + 1e-16f);
    acc.x *= inv; acc.y *= inv; acc.z *= inv; acc.w *= inv;
    __syncthreads();
    *(float4*)&outsm[tid * 4] = acc;
    __syncthreads();

    if (tid < 32) {
#pragma unroll
        for (int i = 0; i < 4; i++) {
            int c = tid * 4 + i;
            float s = outsm[c] + outsm[128 + c] + outsm[256 + c] + outsm[384 + c]
                    + S[(size_t)node * HID + c];
            Out[(size_t)node * HID + c] = fmaxf(s, 0.f);
        }
    }
}

// ---------------- launch ----------------
extern "C" void kernel_launch(void* const* d_in, const int* in_sizes, int n_in,
                              void* d_out, int out_size) {
    const float* x   = (const float*)d_in[0];
    const int*   ei  = (const int*)d_in[1];
    const float* Wq0 = (const float*)d_in[3],  *bq0 = (const float*)d_in[4];
    const float* Wk0 = (const float*)d_in[5],  *bk0 = (const float*)d_in[6];
    const float* Wv0 = (const float*)d_in[7],  *bv0 = (const float*)d_in[8];
    const float* Ws0 = (const float*)d_in[9],  *bs0 = (const float*)d_in[10];
    const float* Wq1 = (const float*)d_in[11], *bq1 = (const float*)d_in[12];
    const float* Wk1 = (const float*)d_in[13], *bk1 = (const float*)d_in[14];
    const float* Wv1 = (const float*)d_in[15], *bv1 = (const float*)d_in[16];
    const float* Ws1 = (const float*)d_in[17], *bs1 = (const float*)d_in[18];
    float* out = (float*)d_out;

    int n = in_sizes[0] / 256;
    int e = in_sizes[1] / 2;

    float *Q, *S, *H, *Wt;
    __nv_bfloat16 *Kh, *Vh;
    int *deg, *off, *cur, *srcs;
    cudaGetSymbolAddress((void**)&Q,    g_Q);
    cudaGetSymbolAddress((void**)&Kh,   g_Kh);
    cudaGetSymbolAddress((void**)&Vh,   g_Vh);
    cudaGetSymbolAddress((void**)&S,    g_S);
    cudaGetSymbolAddress((void**)&H,    g_H);
    cudaGetSymbolAddress((void**)&deg,  g_deg);
    cudaGetSymbolAddress((void**)&off,  g_off);
    cudaGetSymbolAddress((void**)&cur,  g_cur);
    cudaGetSymbolAddress((void**)&srcs, g_srcs);
    cudaGetSymbolAddress((void**)&Wt,   g_Wt);

    // ---- side stream + events for parallel CSR branch (created once, on the
    // uncaptured correctness call; never destroyed -> safe under capture) ----
    static cudaStream_t s1 = 0;
    static cudaEvent_t evFork = 0, evJoin = 0;
    if (s1 == 0) {
        cudaStreamCreateWithFlags(&s1, cudaStreamNonBlocking);
        cudaEventCreateWithFlags(&evFork, cudaEventDisableTiming);
        cudaEventCreateWithFlags(&evJoin, cudaEventDisableTiming);
    }

    int tb = 256;

    // ---- fork: CSR chain on side stream, concurrent with transposes+GEMM0 ----
    cudaEventRecord(evFork, 0);
    cudaStreamWaitEvent(s1, evFork, 0);
    zero_int_kernel<<<(n + tb - 1) / tb, tb, 0, s1>>>(deg, n);
    count_deg_kernel<<<(e + tb - 1) / tb, tb, 0, s1>>>(ei + e, deg, e);
    scan_kernel<<<1, 1024, 0, s1>>>(deg, off, cur, n, e);
    scatter_kernel<<<(e + tb - 1) / tb, tb, 0, s1>>>(ei, cur, srcs, e);
    cudaEventRecord(evJoin, s1);

    // ---- weight transposes (default stream) ----
    dim3 tpb(32, 8);
    {
        dim3 g0(QKV / 32, 256 / 32, 3);
        dim3 gs0(HID / 32, 256 / 32, 1);
        dim3 g1(QKV / 32, 128 / 32, 3);
        dim3 gs1(HID / 32, 128 / 32, 1);
        transpose3_kernel<<<g0, tpb>>>(Wq0, Wk0, Wv0,
                                       Wt + WT_Q0, Wt + WT_K0, Wt + WT_V0, 256, QKV);
        transpose3_kernel<<<gs0, tpb>>>(Ws0, Ws0, Ws0,
                                        Wt + WT_S0, Wt + WT_S0, Wt + WT_S0, 256, HID);
        transpose3_kernel<<<g1, tpb>>>(Wq1, Wk1, Wv1,
                                       Wt + WT_Q1, Wt + WT_K1, Wt + WT_V1, 128, QKV);
        transpose3_kernel<<<gs1, tpb>>>(Ws1, Ws1, Ws1,
                                        Wt + WT_S1, Wt + WT_S1, Wt + WT_S1, 128, HID);
    }

    const int gy = (n + TM - 1) / TM;

    // ---- layer 0 (d_in = 256) ----
    {
        dim3 gqkv(QKV / TN, gy, 3);
        dim3 gs(HID / TN, gy, 1);
        tf32_gemm_kernel<<<gqkv, 256>>>(x, Wt + WT_Q0, Wt + WT_K0, Wt + WT_V0,
                                        bq0, bk0, bv0, Q, Q, Q, Kh, Vh, n, 256, QKV);
        tf32_gemm_kernel<<<gs, 256>>>(x, Wt + WT_S0, Wt + WT_S0, Wt + WT_S0,
                                      bs0, bs0, bs0, S, S, S,
                                      (__nv_bfloat16*)0, (__nv_bfloat16*)0, n, 256, HID);
        cudaStreamWaitEvent(0, evJoin, 0);   // join: attention needs CSR
        attn_fused_kernel<<<n, 128>>>(Q, Kh, Vh, S, off, srcs, H);
    }
    // ---- layer 1 (d_in = 128) ----
    {
        dim3 gqkv(QKV / TN, gy, 3);
        dim3 gs(HID / TN, gy, 1);
        tf32_gemm_kernel<<<gqkv, 256>>>(H, Wt + WT_Q1, Wt + WT_K1, Wt + WT_V1,
                                        bq1, bk1, bv1, Q, Q, Q, Kh, Vh, n, 128, QKV);
        tf32_gemm_kernel<<<gs, 256>>>(H, Wt + WT_S1, Wt + WT_S1, Wt + WT_S1,
                                      bs1, bs1, bs1, S, S, S,
                                      (__nv_bfloat16*)0, (__nv_bfloat16*)0, n, 128, HID);
        attn_fused_kernel<<<n, 128>>>(Q, Kh, Vh, S, off, srcs, out);
    }
}

// round 16
// speedup vs baseline: 1.3102x; 1.0730x over previous
#include <cuda_runtime.h>
#include <cuda_bf16.h>
#include <math.h>
#include <stdint.h>

#define NMAX 10000
#define EMAX 320000
#define HEADS 4
#define HID 128
#define QKV 512  // HEADS*HID
#define ECAP 1024 // smem logit tile capacity (edges)

// ---------------- device scratch (static, no allocation) ----------------
__device__ float  g_Q[NMAX * QKV];
__device__ __nv_bfloat16 g_Kh[NMAX * QKV];
__device__ __nv_bfloat16 g_Vh[NMAX * QKV];
__device__ float  g_S[NMAX * HID];
__device__ float  g_H[NMAX * HID];
__device__ int    g_deg[NMAX];
__device__ int    g_off[NMAX + 1];
__device__ int    g_cur[NMAX];
__device__ int    g_srcs[EMAX];
__device__ float  g_Wt[638976];        // transposed weights [Nc, K] packed

#define WT_Q0 0
#define WT_K0 131072
#define WT_V0 262144
#define WT_S0 393216
#define WT_Q1 425984
#define WT_K1 491520
#define WT_V1 557056
#define WT_S1 622592

__device__ __forceinline__ float2 bf2f2(uint32_t u) {
    __nv_bfloat162 h = *reinterpret_cast<__nv_bfloat162*>(&u);
    return __bfloat1622float2(h);
}

__device__ __forceinline__ uint32_t smem_u32(const void* p) {
    uint32_t a;
    asm("{ .reg .u64 t; cvta.to.shared.u64 t, %1; cvt.u32.u64 %0, t; }"
        : "=r"(a) : "l"(p));
    return a;
}

__device__ __forceinline__ void cp16(uint32_t s, const void* g) {
    asm volatile("cp.async.ca.shared.global [%0], [%1], 16;" :: "r"(s), "l"(g));
}
#define CP_COMMIT() asm volatile("cp.async.commit_group;" ::: "memory")
#define CP_WAIT1()  asm volatile("cp.async.wait_group 1;" ::: "memory")
#define CP_WAIT0()  asm volatile("cp.async.wait_group 0;" ::: "memory")

// ---------------- CSR build ----------------
__global__ void zero_int_kernel(int* p, int n) {
    int i = blockIdx.x * blockDim.x + threadIdx.x;
    if (i < n) p[i] = 0;
}

__global__ void count_deg_kernel(const int* __restrict__ dst, int* __restrict__ deg, int e) {
    int i = blockIdx.x * blockDim.x + threadIdx.x;
    if (i < e) atomicAdd(&deg[dst[i]], 1);
}

__global__ void scan_kernel(const int* __restrict__ deg, int* __restrict__ off,
                            int* __restrict__ cur, int n, int e) {
    __shared__ int part[1024];
    int t = threadIdx.x;
    int chunk = (n + 1023) / 1024;
    int lo = t * chunk;
    int hi = lo + chunk; if (hi > n) hi = n;
    int s = 0;
    for (int i = lo; i < hi; i++) s += deg[i];
    part[t] = s;
    __syncthreads();
    for (int d = 1; d < 1024; d <<= 1) {
        int v = (t >= d) ? part[t - d] : 0;
        __syncthreads();
        part[t] += v;
        __syncthreads();
    }
    int run = part[t] - s;
    for (int i = lo; i < hi; i++) {
        off[i] = run;
        cur[i] = run;
        run += deg[i];
    }
    if (t == 0) off[n] = e;
}

__global__ void scatter_kernel(const int* __restrict__ ei, int* __restrict__ cur,
                               int* __restrict__ srcs, int e) {
    int i = blockIdx.x * blockDim.x + threadIdx.x;
    if (i < e) {
        int s = ei[i];
        int d = ei[e + i];
        int p = atomicAdd(&cur[d], 1);
        srcs[p] = s;
    }
}

// ---------------- weight transpose: Wt[n][k] = W[k][n], z selects matrix -----
__global__ void transpose3_kernel(const float* __restrict__ W0, const float* __restrict__ W1,
                                  const float* __restrict__ W2,
                                  float* __restrict__ T0, float* __restrict__ T1,
                                  float* __restrict__ T2, int K, int Nc) {
    const float* W = (blockIdx.z == 0) ? W0 : (blockIdx.z == 1) ? W1 : W2;
    float* Wt      = (blockIdx.z == 0) ? T0 : (blockIdx.z == 1) ? T1 : T2;
    __shared__ float t[32][33];
    int x = blockIdx.x * 32 + threadIdx.x;
    int y = blockIdx.y * 32 + threadIdx.y;
#pragma unroll
    for (int i = 0; i < 32; i += 8)
        if (y + i < K && x < Nc) t[threadIdx.y + i][threadIdx.x] = W[(size_t)(y + i) * Nc + x];
    __syncthreads();
    x = blockIdx.y * 32 + threadIdx.x;
    y = blockIdx.x * 32 + threadIdx.y;
#pragma unroll
    for (int i = 0; i < 32; i += 8)
        if (y + i < Nc && x < K) Wt[(size_t)(y + i) * K + x] = t[threadIdx.x][threadIdx.y + i];
}

// ---------------- tf32 mma.sync GEMM, cp.async double-buffered ----------------
// z = 0: Q (fp32, Nc=512); z = 1: K (bf16); z = 2: V (bf16); z = 3: S (fp32, Nc=128)
#define TM 128
#define TN 128
#define TBK 16
#define SSTRIDE 20

__device__ __forceinline__ uint32_t f2tf32(float f) {
    uint32_t r;
    asm("cvt.rna.tf32.f32 %0, %1;" : "=r"(r) : "f"(f));
    return r;
}

__device__ __forceinline__ void mma_tf32(float c[4], const uint32_t a[4],
                                         const uint32_t b[2]) {
    asm volatile(
        "mma.sync.aligned.m16n8k8.row.col.f32.tf32.tf32.f32 "
        "{%0,%1,%2,%3}, {%4,%5,%6,%7}, {%8,%9}, {%0,%1,%2,%3};"
        : "+f"(c[0]), "+f"(c[1]), "+f"(c[2]), "+f"(c[3])
        : "r"(a[0]), "r"(a[1]), "r"(a[2]), "r"(a[3]), "r"(b[0]), "r"(b[1]));
}

__global__ __launch_bounds__(256) void tf32_gemm4_kernel(
    const float* __restrict__ A,
    const float* __restrict__ WtQ, const float* __restrict__ WtK,
    const float* __restrict__ WtV, const float* __restrict__ WtS,
    const float* __restrict__ bq, const float* __restrict__ bk,
    const float* __restrict__ bv, const float* __restrict__ bs,
    float* __restrict__ CQ, __nv_bfloat16* __restrict__ ChK,
    __nv_bfloat16* __restrict__ ChV, float* __restrict__ CS,
    int M, int K)
{
    const int z = blockIdx.z;
    if (z == 3 && blockIdx.x != 0) return;   // S slice: only one N-tile

    const float* Wt   = (z == 0) ? WtQ : (z == 1) ? WtK : (z == 2) ? WtV : WtS;
    const float* bias = (z == 0) ? bq  : (z == 1) ? bk  : (z == 2) ? bv  : bs;
    float*       C    = (z == 0) ? CQ  : (z == 3) ? CS  : (float*)0;
    __nv_bfloat16* Ch = (z == 1) ? ChK : (z == 2) ? ChV : (__nv_bfloat16*)0;
    const int Nc      = (z == 3) ? HID : QKV;

    __shared__ float sA[2][TM * SSTRIDE];
    __shared__ float sB[2][TN * SSTRIDE];

    const int tid  = threadIdx.x;
    const int wid  = tid >> 5;
    const int lane = tid & 31;
    const int bm = blockIdx.y * TM;
    const int bn = blockIdx.x * TN;

    const int warp_m = wid >> 2;
    const int warp_n = wid & 3;
    const int m0w = warp_m * 64;
    const int n0w = warp_n * 32;
    const int grp = lane >> 2;
    const int tig = lane & 3;

    const int lr = (tid * 2) >> 2;
    const int lc0 = (tid * 2) & 3;
    const int lr1 = (tid * 2 + 1) >> 2;
    const int lc1 = (tid * 2 + 1) & 3;
    int arow0 = bm + lr;  if (arow0 >= M) arow0 = M - 1;
    int arow1 = bm + lr1; if (arow1 >= M) arow1 = M - 1;
    const uint32_t saA = smem_u32(&sA[0][0]);
    const uint32_t saB = smem_u32(&sB[0][0]);
    const uint32_t bufStride = TM * SSTRIDE * 4;

    float acc[4][4][4];
#pragma unroll
    for (int mt = 0; mt < 4; mt++)
#pragma unroll
        for (int nt = 0; nt < 4; nt++)
#pragma unroll
            for (int i = 0; i < 4; i++) acc[mt][nt][i] = 0.f;

    const int ktiles = K / TBK;

#define LOAD_TILE(KT, BUF)                                                          \
    do {                                                                            \
        const int k0_ = (KT) * TBK;                                                 \
        cp16(saA + (BUF) * bufStride + (lr * SSTRIDE + lc0 * 4) * 4,                \
             &A[(size_t)arow0 * K + k0_ + lc0 * 4]);                                \
        cp16(saA + (BUF) * bufStride + (lr1 * SSTRIDE + lc1 * 4) * 4,               \
             &A[(size_t)arow1 * K + k0_ + lc1 * 4]);                                \
        cp16(saB + (BUF) * bufStride + (lr * SSTRIDE + lc0 * 4) * 4,                \
             &Wt[(size_t)(bn + lr) * K + k0_ + lc0 * 4]);                           \
        cp16(saB + (BUF) * bufStride + (lr1 * SSTRIDE + lc1 * 4) * 4,               \
             &Wt[(size_t)(bn + lr1) * K + k0_ + lc1 * 4]);                          \
    } while (0)

    LOAD_TILE(0, 0);
    CP_COMMIT();

    for (int kt = 0; kt < ktiles; kt++) {
        if (kt + 1 < ktiles) {
            LOAD_TILE(kt + 1, (kt + 1) & 1);
            CP_COMMIT();
            CP_WAIT1();
        } else {
            CP_WAIT0();
        }
        __syncthreads();

        const float* Ab = &sA[kt & 1][0];
        const float* Bb = &sB[kt & 1][0];
#pragma unroll
        for (int ks = 0; ks < 2; ks++) {
            uint32_t af[4][4], bf[4][2];
#pragma unroll
            for (int mt = 0; mt < 4; mt++) {
                int base = (m0w + mt * 16 + grp) * SSTRIDE + ks * 8 + tig;
                af[mt][0] = f2tf32(Ab[base]);
                af[mt][1] = f2tf32(Ab[base + 8 * SSTRIDE]);
                af[mt][2] = f2tf32(Ab[base + 4]);
                af[mt][3] = f2tf32(Ab[base + 8 * SSTRIDE + 4]);
            }
#pragma unroll
            for (int nt = 0; nt < 4; nt++) {
                int base = (n0w + nt * 8 + grp) * SSTRIDE + ks * 8 + tig;
                bf[nt][0] = f2tf32(Bb[base]);
                bf[nt][1] = f2tf32(Bb[base + 4]);
            }
#pragma unroll
            for (int mt = 0; mt < 4; mt++)
#pragma unroll
                for (int nt = 0; nt < 4; nt++)
                    mma_tf32(acc[mt][nt], af[mt], bf[nt]);
        }
        __syncthreads();
    }

#pragma unroll
    for (int mt = 0; mt < 4; mt++) {
        int r0 = bm + m0w + mt * 16 + grp;
        int r1 = r0 + 8;
#pragma unroll
        for (int nt = 0; nt < 4; nt++) {
            int col = bn + n0w + nt * 8 + 2 * tig;
            float2 bi = *(const float2*)&bias[col];
            float vx0 = acc[mt][nt][0] + bi.x, vy0 = acc[mt][nt][1] + bi.y;
            float vx1 = acc[mt][nt][2] + bi.x, vy1 = acc[mt][nt][3] + bi.y;
            if (Ch) {
                if (r0 < M) {
                    __nv_bfloat162 h = __floats2bfloat162_rn(vx0, vy0);
                    *(__nv_bfloat162*)&Ch[(size_t)r0 * Nc + col] = h;
                }
                if (r1 < M) {
                    __nv_bfloat162 h = __floats2bfloat162_rn(vx1, vy1);
                    *(__nv_bfloat162*)&Ch[(size_t)r1 * Nc + col] = h;
                }
            } else {
                if (r0 < M) *(float2*)&C[(size_t)r0 * Nc + col] = make_float2(vx0, vy0);
                if (r1 < M) *(float2*)&C[(size_t)r1 * Nc + col] = make_float2(vx1, vy1);
            }
        }
    }
}

// ---------------- fused attention: smem logits, two-phase per tile -----------
__global__ __launch_bounds__(128) void attn_fused_kernel(
    const float* __restrict__ Q, const __nv_bfloat16* __restrict__ Kh,
    const __nv_bfloat16* __restrict__ Vh, const float* __restrict__ S,
    const int* __restrict__ off, const int* __restrict__ srcs,
    float* __restrict__ Out)
{
    int node = blockIdx.x;
    int tid = threadIdx.x;
    int lane = tid & 31;
    int w = tid >> 5;
    int head = tid >> 5;

    __shared__ float4 sw[ECAP];
    __shared__ float wred[4][4];
    __shared__ float rm_s[4];
    __shared__ float nm_s[4];
    __shared__ float cs_s[4];
    __shared__ float ts_s[4];
    __shared__ float outsm[512];

    const float scale = 0.08838834764831845f;  // 1/sqrt(128)
    float qreg[16];
    {
        const float4* qg = (const float4*)(Q + (size_t)node * QKV);
#pragma unroll
        for (int c = 0; c < 4; c++) {
            float4 v = qg[lane * 4 + c];
            qreg[c * 4 + 0] = v.x * scale;
            qreg[c * 4 + 1] = v.y * scale;
            qreg[c * 4 + 2] = v.z * scale;
            qreg[c * 4 + 3] = v.w * scale;
        }
    }

    if (tid < 4) rm_s[tid] = -1e30f;

    int start = off[node], end = off[node + 1];

    float s_run = 0.f;
    float4 acc = make_float4(0.f, 0.f, 0.f, 0.f);

    for (int t0 = start; t0 < end; t0 += ECAP) {
        int t1 = t0 + ECAP; if (t1 > end) t1 = end;
        int tn = t1 - t0;
        __syncthreads();

        // ---- Phase A: logits into smem ----
        {
            uint4 k0N, k1N;
            int j0 = t0 + w;
            if (j0 < t1) {
                const uint4* kg = (const uint4*)(Kh + (size_t)srcs[j0] * QKV);
                k0N = kg[lane * 2];
                k1N = kg[lane * 2 + 1];
            }
            for (int j = t0 + w; j < t1; j += 4) {
                uint4 k0 = k0N, k1 = k1N;
                if (j + 4 < t1) {
                    const uint4* kg = (const uint4*)(Kh + (size_t)srcs[j + 4] * QKV);
                    k0N = kg[lane * 2];
                    k1N = kg[lane * 2 + 1];
                }
                float part = 0.f;
                {
                    float2 a;
                    a = bf2f2(k0.x); part += qreg[0] * a.x + qreg[1] * a.y;
                    a = bf2f2(k0.y); part += qreg[2] * a.x + qreg[3] * a.y;
                    a = bf2f2(k0.z); part += qreg[4] * a.x + qreg[5] * a.y;
                    a = bf2f2(k0.w); part += qreg[6] * a.x + qreg[7] * a.y;
                    a = bf2f2(k1.x); part += qreg[8] * a.x + qreg[9] * a.y;
                    a = bf2f2(k1.y); part += qreg[10] * a.x + qreg[11] * a.y;
                    a = bf2f2(k1.z); part += qreg[12] * a.x + qreg[13] * a.y;
                    a = bf2f2(k1.w); part += qreg[14] * a.x + qreg[15] * a.y;
                }
                part += __shfl_xor_sync(0xFFFFFFFFu, part, 1);
                part += __shfl_xor_sync(0xFFFFFFFFu, part, 2);
                part += __shfl_xor_sync(0xFFFFFFFFu, part, 4);
                float d0 = __shfl_sync(0xFFFFFFFFu, part, 0);
                float d1 = __shfl_sync(0xFFFFFFFFu, part, 8);
                float d2 = __shfl_sync(0xFFFFFFFFu, part, 16);
                float d3 = __shfl_sync(0xFFFFFFFFu, part, 24);
                if (lane == 0) sw[j - t0] = make_float4(d0, d1, d2, d3);
            }
        }
        __syncthreads();

        // ---- tile max per head ----
        {
            float t0m = -1e30f, t1m = -1e30f, t2m = -1e30f, t3m = -1e30f;
            for (int i = tid; i < tn; i += 128) {
                float4 a = sw[i];
                t0m = fmaxf(t0m, a.x); t1m = fmaxf(t1m, a.y);
                t2m = fmaxf(t2m, a.z); t3m = fmaxf(t3m, a.w);
            }
#pragma unroll
            for (int o = 16; o > 0; o >>= 1) {
                t0m = fmaxf(t0m, __shfl_xor_sync(0xFFFFFFFFu, t0m, o));
                t1m = fmaxf(t1m, __shfl_xor_sync(0xFFFFFFFFu, t1m, o));
                t2m = fmaxf(t2m, __shfl_xor_sync(0xFFFFFFFFu, t2m, o));
                t3m = fmaxf(t3m, __shfl_xor_sync(0xFFFFFFFFu, t3m, o));
            }
            if (lane == 0) {
                wred[w][0] = t0m; wred[w][1] = t1m;
                wred[w][2] = t2m; wred[w][3] = t3m;
            }
        }
        __syncthreads();
        if (tid < 4) {
            float tm = fmaxf(fmaxf(wred[0][tid], wred[1][tid]),
                             fmaxf(wred[2][tid], wred[3][tid]));
            float old = rm_s[tid];
            float nm = fmaxf(old, tm);
            nm_s[tid] = nm;
            cs_s[tid] = __expf(old - nm);
            rm_s[tid] = nm;
        }
        __syncthreads();
        float m0 = nm_s[0], m1 = nm_s[1], m2 = nm_s[2], m3 = nm_s[3];

        // ---- exp conversion + tile sum ----
        {
            float p0 = 0.f, p1 = 0.f, p2 = 0.f, p3 = 0.f;
            for (int i = tid; i < tn; i += 128) {
                float4 a = sw[i];
                a.x = __expf(a.x - m0);
                a.y = __expf(a.y - m1);
                a.z = __expf(a.z - m2);
                a.w = __expf(a.w - m3);
                sw[i] = a;
                p0 += a.x; p1 += a.y; p2 += a.z; p3 += a.w;
            }
#pragma unroll
            for (int o = 16; o > 0; o >>= 1) {
                p0 += __shfl_xor_sync(0xFFFFFFFFu, p0, o);
                p1 += __shfl_xor_sync(0xFFFFFFFFu, p1, o);
                p2 += __shfl_xor_sync(0xFFFFFFFFu, p2, o);
                p3 += __shfl_xor_sync(0xFFFFFFFFu, p3, o);
            }
            if (lane == 0) {
                wred[w][0] = p0; wred[w][1] = p1;
                wred[w][2] = p2; wred[w][3] = p3;
            }
        }
        __syncthreads();
        if (tid < 4)
            ts_s[tid] = wred[0][tid] + wred[1][tid] + wred[2][tid] + wred[3][tid];
        __syncthreads();

        {
            float cs = cs_s[head];
            s_run = s_run * cs + ts_s[head];
            acc.x *= cs; acc.y *= cs; acc.z *= cs; acc.w *= cs;
        }

        // ---- Phase B: V gather, unroll 8, weights from smem ----
        const float* swf = (const float*)sw;
        int j = t0;
        for (; j + 7 < t1; j += 8) {
            int b = j - t0;
            int s0 = srcs[j],     s1 = srcs[j + 1], s2 = srcs[j + 2], s3 = srcs[j + 3];
            int s4 = srcs[j + 4], s5 = srcs[j + 5], s6 = srcs[j + 6], s7 = srcs[j + 7];
            uint2 u0 = ((const uint2*)(Vh + (size_t)s0 * QKV))[tid];
            uint2 u1 = ((const uint2*)(Vh + (size_t)s1 * QKV))[tid];
            uint2 u2 = ((const uint2*)(Vh + (size_t)s2 * QKV))[tid];
            uint2 u3 = ((const uint2*)(Vh + (size_t)s3 * QKV))[tid];
            uint2 u4 = ((const uint2*)(Vh + (size_t)s4 * QKV))[tid];
            uint2 u5 = ((const uint2*)(Vh + (size_t)s5 * QKV))[tid];
            uint2 u6 = ((const uint2*)(Vh + (size_t)s6 * QKV))[tid];
            uint2 u7 = ((const uint2*)(Vh + (size_t)s7 * QKV))[tid];
            float g0 = swf[(b + 0) * 4 + head];
            float g1 = swf[(b + 1) * 4 + head];
            float g2 = swf[(b + 2) * 4 + head];
            float g3 = swf[(b + 3) * 4 + head];
            float g4 = swf[(b + 4) * 4 + head];
            float g5 = swf[(b + 5) * 4 + head];
            float g6 = swf[(b + 6) * 4 + head];
            float g7 = swf[(b + 7) * 4 + head];
            float2 a0 = bf2f2(u0.x), b0 = bf2f2(u0.y);
            float2 a1 = bf2f2(u1.x), b1 = bf2f2(u1.y);
            float2 a2 = bf2f2(u2.x), b2 = bf2f2(u2.y);
            float2 a3 = bf2f2(u3.x), b3 = bf2f2(u3.y);
            float2 a4 = bf2f2(u4.x), b4 = bf2f2(u4.y);
            float2 a5 = bf2f2(u5.x), b5 = bf2f2(u5.y);
            float2 a6 = bf2f2(u6.x), b6 = bf2f2(u6.y);
            float2 a7 = bf2f2(u7.x), b7 = bf2f2(u7.y);
            acc.x += g0 * a0.x + g1 * a1.x + g2 * a2.x + g3 * a3.x
                   + g4 * a4.x + g5 * a5.x + g6 * a6.x + g7 * a7.x;
            acc.y += g0 * a0.y + g1 * a1.y + g2 * a2.y + g3 * a3.y
                   + g4 * a4.y + g5 * a5.y + g6 * a6.y + g7 * a7.y;
            acc.z += g0 * b0.x + g1 * b1.x + g2 * b2.x + g3 * b3.x
                   + g4 * b4.x + g5 * b5.x + g6 * b6.x + g7 * b7.x;
            acc.w += g0 * b0.y + g1 * b1.y + g2 * b2.y + g3 * b3.y
                   + g4 * b4.y + g5 * b5.y + g6 * b6.y + g7 * b7.y;
        }
        for (; j < t1; j++) {
            int s0 = srcs[j];
            uint2 u0 = ((const uint2*)(Vh + (size_t)s0 * QKV))[tid];
            float g0 = swf[(j - t0) * 4 + head];
            float2 a0 = bf2f2(u0.x), b0 = bf2f2(u0.y);
            acc.x += g0 * a0.x;
            acc.y += g0 * a0.y;
            acc.z += g0 * b0.x;
            acc.w += g0 * b0.y;
        }
    }

    float inv = 0.25f / (s_run + 1e-16f);
    acc.x *= inv; acc.y *= inv; acc.z *= inv; acc.w *= inv;
    __syncthreads();
    *(float4*)&outsm[tid * 4] = acc;
    __syncthreads();

    if (tid < 32) {
#pragma unroll
        for (int i = 0; i < 4; i++) {
            int c = tid * 4 + i;
            float s = outsm[c] + outsm[128 + c] + outsm[256 + c] + outsm[384 + c]
                    + S[(size_t)node * HID + c];
            Out[(size_t)node * HID + c] = fmaxf(s, 0.f);
        }
    }
}

// ---------------- launch ----------------
extern "C" void kernel_launch(void* const* d_in, const int* in_sizes, int n_in,
                              void* d_out, int out_size) {
    const float* x   = (const float*)d_in[0];
    const int*   ei  = (const int*)d_in[1];
    const float* Wq0 = (const float*)d_in[3],  *bq0 = (const float*)d_in[4];
    const float* Wk0 = (const float*)d_in[5],  *bk0 = (const float*)d_in[6];
    const float* Wv0 = (const float*)d_in[7],  *bv0 = (const float*)d_in[8];
    const float* Ws0 = (const float*)d_in[9],  *bs0 = (const float*)d_in[10];
    const float* Wq1 = (const float*)d_in[11], *bq1 = (const float*)d_in[12];
    const float* Wk1 = (const float*)d_in[13], *bk1 = (const float*)d_in[14];
    const float* Wv1 = (const float*)d_in[15], *bv1 = (const float*)d_in[16];
    const float* Ws1 = (const float*)d_in[17], *bs1 = (const float*)d_in[18];
    float* out = (float*)d_out;

    int n = in_sizes[0] / 256;
    int e = in_sizes[1] / 2;

    float *Q, *S, *H, *Wt;
    __nv_bfloat16 *Kh, *Vh;
    int *deg, *off, *cur, *srcs;
    cudaGetSymbolAddress((void**)&Q,    g_Q);
    cudaGetSymbolAddress((void**)&Kh,   g_Kh);
    cudaGetSymbolAddress((void**)&Vh,   g_Vh);
    cudaGetSymbolAddress((void**)&S,    g_S);
    cudaGetSymbolAddress((void**)&H,    g_H);
    cudaGetSymbolAddress((void**)&deg,  g_deg);
    cudaGetSymbolAddress((void**)&off,  g_off);
    cudaGetSymbolAddress((void**)&cur,  g_cur);
    cudaGetSymbolAddress((void**)&srcs, g_srcs);
    cudaGetSymbolAddress((void**)&Wt,   g_Wt);

    // ---- side stream + events (created once on uncaptured correctness call) --
    static cudaStream_t s1 = 0;
    static cudaEvent_t evFork = 0, evJoin = 0;
    if (s1 == 0) {
        cudaStreamCreateWithFlags(&s1, cudaStreamNonBlocking);
        cudaEventCreateWithFlags(&evFork, cudaEventDisableTiming);
        cudaEventCreateWithFlags(&evJoin, cudaEventDisableTiming);
    }

    int tb = 256;

    // ---- fork: CSR chain on side stream, concurrent with transposes+GEMM0 ----
    cudaEventRecord(evFork, 0);
    cudaStreamWaitEvent(s1, evFork, 0);
    zero_int_kernel<<<(n + tb - 1) / tb, tb, 0, s1>>>(deg, n);
    count_deg_kernel<<<(e + tb - 1) / tb, tb, 0, s1>>>(ei + e, deg, e);
    scan_kernel<<<1, 1024, 0, s1>>>(deg, off, cur, n, e);
    scatter_kernel<<<(e + tb - 1) / tb, tb, 0, s1>>>(ei, cur, srcs, e);
    cudaEventRecord(evJoin, s1);

    // ---- weight transposes (default stream) ----
    dim3 tpb(32, 8);
    {
        dim3 g0(QKV / 32, 256 / 32, 3);
        dim3 gs0(HID / 32, 256 / 32, 1);
        dim3 g1(QKV / 32, 128 / 32, 3);
        dim3 gs1(HID / 32, 128 / 32, 1);
        transpose3_kernel<<<g0, tpb>>>(Wq0, Wk0, Wv0,
                                       Wt + WT_Q0, Wt + WT_K0, Wt + WT_V0, 256, QKV);
        transpose3_kernel<<<gs0, tpb>>>(Ws0, Ws0, Ws0,
                                        Wt + WT_S0, Wt + WT_S0, Wt + WT_S0, 256, HID);
        transpose3_kernel<<<g1, tpb>>>(Wq1, Wk1, Wv1,
                                       Wt + WT_Q1, Wt + WT_K1, Wt + WT_V1, 128, QKV);
        transpose3_kernel<<<gs1, tpb>>>(Ws1, Ws1, Ws1,
                                        Wt + WT_S1, Wt + WT_S1, Wt + WT_S1, 128, HID);
    }

    const int gy = (n + TM - 1) / TM;

    // ---- layer 0 (d_in = 256): QKV + S in one launch ----
    {
        dim3 g(QKV / TN, gy, 4);
        tf32_gemm4_kernel<<<g, 256>>>(x,
                                      Wt + WT_Q0, Wt + WT_K0, Wt + WT_V0, Wt + WT_S0,
                                      bq0, bk0, bv0, bs0,
                                      Q, Kh, Vh, S, n, 256);
        cudaStreamWaitEvent(0, evJoin, 0);   // join: attention needs CSR
        attn_fused_kernel<<<n, 128>>>(Q, Kh, Vh, S, off, srcs, H);
    }
    // ---- layer 1 (d_in = 128): QKV + S in one launch ----
    {
        dim3 g(QKV / TN, gy, 4);
        tf32_gemm4_kernel<<<g, 256>>>(H,
                                      Wt + WT_Q1, Wt + WT_K1, Wt + WT_V1, Wt + WT_S1,
                                      bq1, bk1, bv1, bs1,
                                      Q, Kh, Vh, S, n, 128);
        attn_fused_kernel<<<n, 128>>>(Q, Kh, Vh, S, off, srcs, out);
    }
}

// round 17
// speedup vs baseline: 1.3267x; 1.0126x over previous
#include <cuda_runtime.h>
#include <cuda_bf16.h>
#include <math.h>
#include <stdint.h>

#define NMAX 10000
#define EMAX 320000
#define HEADS 4
#define HID 128
#define QKV 512  // HEADS*HID
#define ECAP 1024 // smem logit tile capacity (edges)

// ---------------- device scratch (static, no allocation) ----------------
__device__ float  g_Q[NMAX * QKV];
__device__ __nv_bfloat16 g_Kh[NMAX * QKV];
__device__ __nv_bfloat16 g_Vh[NMAX * QKV];
__device__ float  g_S[NMAX * HID];
__device__ float  g_H[NMAX * HID];
__device__ int    g_deg[NMAX];
__device__ int    g_off[NMAX + 1];
__device__ int    g_cur[NMAX];
__device__ int    g_srcs[EMAX];
__device__ float  g_Wt[638976];        // transposed weights [Nc, K] packed

#define WT_Q0 0
#define WT_K0 131072
#define WT_V0 262144
#define WT_S0 393216
#define WT_Q1 425984
#define WT_K1 491520
#define WT_V1 557056
#define WT_S1 622592

__device__ __forceinline__ float2 bf2f2(uint32_t u) {
    __nv_bfloat162 h = *reinterpret_cast<__nv_bfloat162*>(&u);
    return __bfloat1622float2(h);
}

__device__ __forceinline__ uint32_t smem_u32(const void* p) {
    uint32_t a;
    asm("{ .reg .u64 t; cvta.to.shared.u64 t, %1; cvt.u32.u64 %0, t; }"
        : "=r"(a) : "l"(p));
    return a;
}

__device__ __forceinline__ void cp16(uint32_t s, const void* g) {
    asm volatile("cp.async.ca.shared.global [%0], [%1], 16;" :: "r"(s), "l"(g));
}
#define CP_COMMIT() asm volatile("cp.async.commit_group;" ::: "memory")
#define CP_WAIT1()  asm volatile("cp.async.wait_group 1;" ::: "memory")
#define CP_WAIT0()  asm volatile("cp.async.wait_group 0;" ::: "memory")

// ---------------- CSR build ----------------
__global__ void zero_int_kernel(int* p, int n) {
    int i = blockIdx.x * blockDim.x + threadIdx.x;
    if (i < n) p[i] = 0;
}

__global__ void count_deg_kernel(const int* __restrict__ dst, int* __restrict__ deg, int e) {
    int i = blockIdx.x * blockDim.x + threadIdx.x;
    if (i < e) atomicAdd(&deg[dst[i]], 1);
}

__global__ void scan_kernel(const int* __restrict__ deg, int* __restrict__ off,
                            int* __restrict__ cur, int n, int e) {
    __shared__ int part[1024];
    int t = threadIdx.x;
    int chunk = (n + 1023) / 1024;
    int lo = t * chunk;
    int hi = lo + chunk; if (hi > n) hi = n;
    int s = 0;
    for (int i = lo; i < hi; i++) s += deg[i];
    part[t] = s;
    __syncthreads();
    for (int d = 1; d < 1024; d <<= 1) {
        int v = (t >= d) ? part[t - d] : 0;
        __syncthreads();
        part[t] += v;
        __syncthreads();
    }
    int run = part[t] - s;
    for (int i = lo; i < hi; i++) {
        off[i] = run;
        cur[i] = run;
        run += deg[i];
    }
    if (t == 0) off[n] = e;
}

__global__ void scatter_kernel(const int* __restrict__ ei, int* __restrict__ cur,
                               int* __restrict__ srcs, int e) {
    int i = blockIdx.x * blockDim.x + threadIdx.x;
    if (i < e) {
        int s = ei[i];
        int d = ei[e + i];
        int p = atomicAdd(&cur[d], 1);
        srcs[p] = s;
    }
}

// ---------------- weight transpose: Wt[n][k] = W[k][n], z selects matrix -----
__global__ void transpose3_kernel(const float* __restrict__ W0, const float* __restrict__ W1,
                                  const float* __restrict__ W2,
                                  float* __restrict__ T0, float* __restrict__ T1,
                                  float* __restrict__ T2, int K, int Nc) {
    const float* W = (blockIdx.z == 0) ? W0 : (blockIdx.z == 1) ? W1 : W2;
    float* Wt      = (blockIdx.z == 0) ? T0 : (blockIdx.z == 1) ? T1 : T2;
    __shared__ float t[32][33];
    int x = blockIdx.x * 32 + threadIdx.x;
    int y = blockIdx.y * 32 + threadIdx.y;
#pragma unroll
    for (int i = 0; i < 32; i += 8)
        if (y + i < K && x < Nc) t[threadIdx.y + i][threadIdx.x] = W[(size_t)(y + i) * Nc + x];
    __syncthreads();
    x = blockIdx.y * 32 + threadIdx.x;
    y = blockIdx.x * 32 + threadIdx.y;
#pragma unroll
    for (int i = 0; i < 32; i += 8)
        if (y + i < Nc && x < K) Wt[(size_t)(y + i) * K + x] = t[threadIdx.x][threadIdx.y + i];
}

// ---------------- tf32 mma.sync GEMM, cp.async double-buffered ----------------
// z = 0: Q (fp32, Nc=512); z = 1: K (bf16); z = 2: V (bf16); z = 3: S (fp32, Nc=128)
// ybase: row-tile offset (rows [ybase*TM, (ybase+gridDim.y)*TM))
#define TM 128
#define TN 128
#define TBK 16
#define SSTRIDE 20

__device__ __forceinline__ uint32_t f2tf32(float f) {
    uint32_t r;
    asm("cvt.rna.tf32.f32 %0, %1;" : "=r"(r) : "f"(f));
    return r;
}

__device__ __forceinline__ void mma_tf32(float c[4], const uint32_t a[4],
                                         const uint32_t b[2]) {
    asm volatile(
        "mma.sync.aligned.m16n8k8.row.col.f32.tf32.tf32.f32 "
        "{%0,%1,%2,%3}, {%4,%5,%6,%7}, {%8,%9}, {%0,%1,%2,%3};"
        : "+f"(c[0]), "+f"(c[1]), "+f"(c[2]), "+f"(c[3])
        : "r"(a[0]), "r"(a[1]), "r"(a[2]), "r"(a[3]), "r"(b[0]), "r"(b[1]));
}

__global__ __launch_bounds__(256) void tf32_gemm4_kernel(
    const float* __restrict__ A,
    const float* __restrict__ WtQ, const float* __restrict__ WtK,
    const float* __restrict__ WtV, const float* __restrict__ WtS,
    const float* __restrict__ bq, const float* __restrict__ bk,
    const float* __restrict__ bv, const float* __restrict__ bs,
    float* __restrict__ CQ, __nv_bfloat16* __restrict__ ChK,
    __nv_bfloat16* __restrict__ ChV, float* __restrict__ CS,
    int M, int K, int ybase)
{
    const int z = blockIdx.z;
    if (z == 3 && blockIdx.x != 0) return;   // S slice: only one N-tile

    const float* Wt   = (z == 0) ? WtQ : (z == 1) ? WtK : (z == 2) ? WtV : WtS;
    const float* bias = (z == 0) ? bq  : (z == 1) ? bk  : (z == 2) ? bv  : bs;
    float*       C    = (z == 0) ? CQ  : (z == 3) ? CS  : (float*)0;
    __nv_bfloat16* Ch = (z == 1) ? ChK : (z == 2) ? ChV : (__nv_bfloat16*)0;
    const int Nc      = (z == 3) ? HID : QKV;

    __shared__ float sA[2][TM * SSTRIDE];
    __shared__ float sB[2][TN * SSTRIDE];

    const int tid  = threadIdx.x;
    const int wid  = tid >> 5;
    const int lane = tid & 31;
    const int bm = (blockIdx.y + ybase) * TM;
    const int bn = blockIdx.x * TN;

    const int warp_m = wid >> 2;
    const int warp_n = wid & 3;
    const int m0w = warp_m * 64;
    const int n0w = warp_n * 32;
    const int grp = lane >> 2;
    const int tig = lane & 3;

    const int lr = (tid * 2) >> 2;
    const int lc0 = (tid * 2) & 3;
    const int lr1 = (tid * 2 + 1) >> 2;
    const int lc1 = (tid * 2 + 1) & 3;
    int arow0 = bm + lr;  if (arow0 >= M) arow0 = M - 1;
    int arow1 = bm + lr1; if (arow1 >= M) arow1 = M - 1;
    const uint32_t saA = smem_u32(&sA[0][0]);
    const uint32_t saB = smem_u32(&sB[0][0]);
    const uint32_t bufStride = TM * SSTRIDE * 4;

    float acc[4][4][4];
#pragma unroll
    for (int mt = 0; mt < 4; mt++)
#pragma unroll
        for (int nt = 0; nt < 4; nt++)
#pragma unroll
            for (int i = 0; i < 4; i++) acc[mt][nt][i] = 0.f;

    const int ktiles = K / TBK;

#define LOAD_TILE(KT, BUF)                                                          \
    do {                                                                            \
        const int k0_ = (KT) * TBK;                                                 \
        cp16(saA + (BUF) * bufStride + (lr * SSTRIDE + lc0 * 4) * 4,                \
             &A[(size_t)arow0 * K + k0_ + lc0 * 4]);                                \
        cp16(saA + (BUF) * bufStride + (lr1 * SSTRIDE + lc1 * 4) * 4,               \
             &A[(size_t)arow1 * K + k0_ + lc1 * 4]);                                \
        cp16(saB + (BUF) * bufStride + (lr * SSTRIDE + lc0 * 4) * 4,                \
             &Wt[(size_t)(bn + lr) * K + k0_ + lc0 * 4]);                           \
        cp16(saB + (BUF) * bufStride + (lr1 * SSTRIDE + lc1 * 4) * 4,               \
             &Wt[(size_t)(bn + lr1) * K + k0_ + lc1 * 4]);                          \
    } while (0)

    LOAD_TILE(0, 0);
    CP_COMMIT();

    for (int kt = 0; kt < ktiles; kt++) {
        if (kt + 1 < ktiles) {
            LOAD_TILE(kt + 1, (kt + 1) & 1);
            CP_COMMIT();
            CP_WAIT1();
        } else {
            CP_WAIT0();
        }
        __syncthreads();

        const float* Ab = &sA[kt & 1][0];
        const float* Bb = &sB[kt & 1][0];
#pragma unroll
        for (int ks = 0; ks < 2; ks++) {
            uint32_t af[4][4], bf[4][2];
#pragma unroll
            for (int mt = 0; mt < 4; mt++) {
                int base = (m0w + mt * 16 + grp) * SSTRIDE + ks * 8 + tig;
                af[mt][0] = f2tf32(Ab[base]);
                af[mt][1] = f2tf32(Ab[base + 8 * SSTRIDE]);
                af[mt][2] = f2tf32(Ab[base + 4]);
                af[mt][3] = f2tf32(Ab[base + 8 * SSTRIDE + 4]);
            }
#pragma unroll
            for (int nt = 0; nt < 4; nt++) {
                int base = (n0w + nt * 8 + grp) * SSTRIDE + ks * 8 + tig;
                bf[nt][0] = f2tf32(Bb[base]);
                bf[nt][1] = f2tf32(Bb[base + 4]);
            }
#pragma unroll
            for (int mt = 0; mt < 4; mt++)
#pragma unroll
                for (int nt = 0; nt < 4; nt++)
                    mma_tf32(acc[mt][nt], af[mt], bf[nt]);
        }
        __syncthreads();
    }

#pragma unroll
    for (int mt = 0; mt < 4; mt++) {
        int r0 = bm + m0w + mt * 16 + grp;
        int r1 = r0 + 8;
#pragma unroll
        for (int nt = 0; nt < 4; nt++) {
            int col = bn + n0w + nt * 8 + 2 * tig;
            float2 bi = *(const float2*)&bias[col];
            float vx0 = acc[mt][nt][0] + bi.x, vy0 = acc[mt][nt][1] + bi.y;
            float vx1 = acc[mt][nt][2] + bi.x, vy1 = acc[mt][nt][3] + bi.y;
            if (Ch) {
                if (r0 < M) {
                    __nv_bfloat162 h = __floats2bfloat162_rn(vx0, vy0);
                    *(__nv_bfloat162*)&Ch[(size_t)r0 * Nc + col] = h;
                }
                if (r1 < M) {
                    __nv_bfloat162 h = __floats2bfloat162_rn(vx1, vy1);
                    *(__nv_bfloat162*)&Ch[(size_t)r1 * Nc + col] = h;
                }
            } else {
                if (r0 < M) *(float2*)&C[(size_t)r0 * Nc + col] = make_float2(vx0, vy0);
                if (r1 < M) *(float2*)&C[(size_t)r1 * Nc + col] = make_float2(vx1, vy1);
            }
        }
    }
}

// ---------------- fused attention: smem logits, two-phase per tile -----------
__global__ __launch_bounds__(128) void attn_fused_kernel(
    const float* __restrict__ Q, const __nv_bfloat16* __restrict__ Kh,
    const __nv_bfloat16* __restrict__ Vh, const float* __restrict__ S,
    const int* __restrict__ off, const int* __restrict__ srcs,
    float* __restrict__ Out, int node0)
{
    int node = blockIdx.x + node0;
    int tid = threadIdx.x;
    int lane = tid & 31;
    int w = tid >> 5;
    int head = tid >> 5;

    __shared__ float4 sw[ECAP];
    __shared__ float wred[4][4];
    __shared__ float rm_s[4];
    __shared__ float nm_s[4];
    __shared__ float cs_s[4];
    __shared__ float ts_s[4];
    __shared__ float outsm[512];

    const float scale = 0.08838834764831845f;  // 1/sqrt(128)
    float qreg[16];
    {
        const float4* qg = (const float4*)(Q + (size_t)node * QKV);
#pragma unroll
        for (int c = 0; c < 4; c++) {
            float4 v = qg[lane * 4 + c];
            qreg[c * 4 + 0] = v.x * scale;
            qreg[c * 4 + 1] = v.y * scale;
            qreg[c * 4 + 2] = v.z * scale;
            qreg[c * 4 + 3] = v.w * scale;
        }
    }

    if (tid < 4) rm_s[tid] = -1e30f;

    int start = off[node], end = off[node + 1];

    float s_run = 0.f;
    float4 acc = make_float4(0.f, 0.f, 0.f, 0.f);

    for (int t0 = start; t0 < end; t0 += ECAP) {
        int t1 = t0 + ECAP; if (t1 > end) t1 = end;
        int tn = t1 - t0;
        __syncthreads();

        // ---- Phase A: logits into smem ----
        {
            uint4 k0N, k1N;
            int j0 = t0 + w;
            if (j0 < t1) {
                const uint4* kg = (const uint4*)(Kh + (size_t)srcs[j0] * QKV);
                k0N = kg[lane * 2];
                k1N = kg[lane * 2 + 1];
            }
            for (int j = t0 + w; j < t1; j += 4) {
                uint4 k0 = k0N, k1 = k1N;
                if (j + 4 < t1) {
                    const uint4* kg = (const uint4*)(Kh + (size_t)srcs[j + 4] * QKV);
                    k0N = kg[lane * 2];
                    k1N = kg[lane * 2 + 1];
                }
                float part = 0.f;
                {
                    float2 a;
                    a = bf2f2(k0.x); part += qreg[0] * a.x + qreg[1] * a.y;
                    a = bf2f2(k0.y); part += qreg[2] * a.x + qreg[3] * a.y;
                    a = bf2f2(k0.z); part += qreg[4] * a.x + qreg[5] * a.y;
                    a = bf2f2(k0.w); part += qreg[6] * a.x + qreg[7] * a.y;
                    a = bf2f2(k1.x); part += qreg[8] * a.x + qreg[9] * a.y;
                    a = bf2f2(k1.y); part += qreg[10] * a.x + qreg[11] * a.y;
                    a = bf2f2(k1.z); part += qreg[12] * a.x + qreg[13] * a.y;
                    a = bf2f2(k1.w); part += qreg[14] * a.x + qreg[15] * a.y;
                }
                part += __shfl_xor_sync(0xFFFFFFFFu, part, 1);
                part += __shfl_xor_sync(0xFFFFFFFFu, part, 2);
                part += __shfl_xor_sync(0xFFFFFFFFu, part, 4);
                float d0 = __shfl_sync(0xFFFFFFFFu, part, 0);
                float d1 = __shfl_sync(0xFFFFFFFFu, part, 8);
                float d2 = __shfl_sync(0xFFFFFFFFu, part, 16);
                float d3 = __shfl_sync(0xFFFFFFFFu, part, 24);
                if (lane == 0) sw[j - t0] = make_float4(d0, d1, d2, d3);
            }
        }
        __syncthreads();

        // ---- tile max per head ----
        {
            float t0m = -1e30f, t1m = -1e30f, t2m = -1e30f, t3m = -1e30f;
            for (int i = tid; i < tn; i += 128) {
                float4 a = sw[i];
                t0m = fmaxf(t0m, a.x); t1m = fmaxf(t1m, a.y);
                t2m = fmaxf(t2m, a.z); t3m = fmaxf(t3m, a.w);
            }
#pragma unroll
            for (int o = 16; o > 0; o >>= 1) {
                t0m = fmaxf(t0m, __shfl_xor_sync(0xFFFFFFFFu, t0m, o));
                t1m = fmaxf(t1m, __shfl_xor_sync(0xFFFFFFFFu, t1m, o));
                t2m = fmaxf(t2m, __shfl_xor_sync(0xFFFFFFFFu, t2m, o));
                t3m = fmaxf(t3m, __shfl_xor_sync(0xFFFFFFFFu, t3m, o));
            }
            if (lane == 0) {
                wred[w][0] = t0m; wred[w][1] = t1m;
                wred[w][2] = t2m; wred[w][3] = t3m;
            }
        }
        __syncthreads();
        if (tid < 4) {
            float tm = fmaxf(fmaxf(wred[0][tid], wred[1][tid]),
                             fmaxf(wred[2][tid], wred[3][tid]));
            float old = rm_s[tid];
            float nm = fmaxf(old, tm);
            nm_s[tid] = nm;
            cs_s[tid] = __expf(old - nm);
            rm_s[tid] = nm;
        }
        __syncthreads();
        float m0 = nm_s[0], m1 = nm_s[1], m2 = nm_s[2], m3 = nm_s[3];

        // ---- exp conversion + tile sum ----
        {
            float p0 = 0.f, p1 = 0.f, p2 = 0.f, p3 = 0.f;
            for (int i = tid; i < tn; i += 128) {
                float4 a = sw[i];
                a.x = __expf(a.x - m0);
                a.y = __expf(a.y - m1);
                a.z = __expf(a.z - m2);
                a.w = __expf(a.w - m3);
                sw[i] = a;
                p0 += a.x; p1 += a.y; p2 += a.z; p3 += a.w;
            }
#pragma unroll
            for (int o = 16; o > 0; o >>= 1) {
                p0 += __shfl_xor_sync(0xFFFFFFFFu, p0, o);
                p1 += __shfl_xor_sync(0xFFFFFFFFu, p1, o);
                p2 += __shfl_xor_sync(0xFFFFFFFFu, p2, o);
                p3 += __shfl_xor_sync(0xFFFFFFFFu, p3, o);
            }
            if (lane == 0) {
                wred[w][0] = p0; wred[w][1] = p1;
                wred[w][2] = p2; wred[w][3] = p3;
            }
        }
        __syncthreads();
        if (tid < 4)
            ts_s[tid] = wred[0][tid] + wred[1][tid] + wred[2][tid] + wred[3][tid];
        __syncthreads();

        {
            float cs = cs_s[head];
            s_run = s_run * cs + ts_s[head];
            acc.x *= cs; acc.y *= cs; acc.z *= cs; acc.w *= cs;
        }

        // ---- Phase B: V gather, unroll 8, weights from smem ----
        const float* swf = (const float*)sw;
        int j = t0;
        for (; j + 7 < t1; j += 8) {
            int b = j - t0;
            int s0 = srcs[j],     s1 = srcs[j + 1], s2 = srcs[j + 2], s3 = srcs[j + 3];
            int s4 = srcs[j + 4], s5 = srcs[j + 5], s6 = srcs[j + 6], s7 = srcs[j + 7];
            uint2 u0 = ((const uint2*)(Vh + (size_t)s0 * QKV))[tid];
            uint2 u1 = ((const uint2*)(Vh + (size_t)s1 * QKV))[tid];
            uint2 u2 = ((const uint2*)(Vh + (size_t)s2 * QKV))[tid];
            uint2 u3 = ((const uint2*)(Vh + (size_t)s3 * QKV))[tid];
            uint2 u4 = ((const uint2*)(Vh + (size_t)s4 * QKV))[tid];
            uint2 u5 = ((const uint2*)(Vh + (size_t)s5 * QKV))[tid];
            uint2 u6 = ((const uint2*)(Vh + (size_t)s6 * QKV))[tid];
            uint2 u7 = ((const uint2*)(Vh + (size_t)s7 * QKV))[tid];
            float g0 = swf[(b + 0) * 4 + head];
            float g1 = swf[(b + 1) * 4 + head];
            float g2 = swf[(b + 2) * 4 + head];
            float g3 = swf[(b + 3) * 4 + head];
            float g4 = swf[(b + 4) * 4 + head];
            float g5 = swf[(b + 5) * 4 + head];
            float g6 = swf[(b + 6) * 4 + head];
            float g7 = swf[(b + 7) * 4 + head];
            float2 a0 = bf2f2(u0.x), b0 = bf2f2(u0.y);
            float2 a1 = bf2f2(u1.x), b1 = bf2f2(u1.y);
            float2 a2 = bf2f2(u2.x), b2 = bf2f2(u2.y);
            float2 a3 = bf2f2(u3.x), b3 = bf2f2(u3.y);
            float2 a4 = bf2f2(u4.x), b4 = bf2f2(u4.y);
            float2 a5 = bf2f2(u5.x), b5 = bf2f2(u5.y);
            float2 a6 = bf2f2(u6.x), b6 = bf2f2(u6.y);
            float2 a7 = bf2f2(u7.x), b7 = bf2f2(u7.y);
            acc.x += g0 * a0.x + g1 * a1.x + g2 * a2.x + g3 * a3.x
                   + g4 * a4.x + g5 * a5.x + g6 * a6.x + g7 * a7.x;
            acc.y += g0 * a0.y + g1 * a1.y + g2 * a2.y + g3 * a3.y
                   + g4 * a4.y + g5 * a5.y + g6 * a6.y + g7 * a7.y;
            acc.z += g0 * b0.x + g1 * b1.x + g2 * b2.x + g3 * b3.x
                   + g4 * b4.x + g5 * b5.x + g6 * b6.x + g7 * b7.x;
            acc.w += g0 * b0.y + g1 * b1.y + g2 * b2.y + g3 * b3.y
                   + g4 * b4.y + g5 * b5.y + g6 * b6.y + g7 * b7.y;
        }
        for (; j < t1; j++) {
            int s0 = srcs[j];
            uint2 u0 = ((const uint2*)(Vh + (size_t)s0 * QKV))[tid];
            float g0 = swf[(j - t0) * 4 + head];
            float2 a0 = bf2f2(u0.x), b0 = bf2f2(u0.y);
            acc.x += g0 * a0.x;
            acc.y += g0 * a0.y;
            acc.z += g0 * b0.x;
            acc.w += g0 * b0.y;
        }
    }

    float inv = 0.25f / (s_run + 1e-16f);
    acc.x *= inv; acc.y *= inv; acc.z *= inv; acc.w *= inv;
    __syncthreads();
    *(float4*)&outsm[tid * 4] = acc;
    __syncthreads();

    if (tid < 32) {
#pragma unroll
        for (int i = 0; i < 4; i++) {
            int c = tid * 4 + i;
            float s = outsm[c] + outsm[128 + c] + outsm[256 + c] + outsm[384 + c]
                    + S[(size_t)node * HID + c];
            Out[(size_t)node * HID + c] = fmaxf(s, 0.f);
        }
    }
}

// ---------------- launch ----------------
extern "C" void kernel_launch(void* const* d_in, const int* in_sizes, int n_in,
                              void* d_out, int out_size) {
    const float* x   = (const float*)d_in[0];
    const int*   ei  = (const int*)d_in[1];
    const float* Wq0 = (const float*)d_in[3],  *bq0 = (const float*)d_in[4];
    const float* Wk0 = (const float*)d_in[5],  *bk0 = (const float*)d_in[6];
    const float* Wv0 = (const float*)d_in[7],  *bv0 = (const float*)d_in[8];
    const float* Ws0 = (const float*)d_in[9],  *bs0 = (const float*)d_in[10];
    const float* Wq1 = (const float*)d_in[11], *bq1 = (const float*)d_in[12];
    const float* Wk1 = (const float*)d_in[13], *bk1 = (const float*)d_in[14];
    const float* Wv1 = (const float*)d_in[15], *bv1 = (const float*)d_in[16];
    const float* Ws1 = (const float*)d_in[17], *bs1 = (const float*)d_in[18];
    float* out = (float*)d_out;

    int n = in_sizes[0] / 256;
    int e = in_sizes[1] / 2;

    float *Q, *S, *H, *Wt;
    __nv_bfloat16 *Kh, *Vh;
    int *deg, *off, *cur, *srcs;
    cudaGetSymbolAddress((void**)&Q,    g_Q);
    cudaGetSymbolAddress((void**)&Kh,   g_Kh);
    cudaGetSymbolAddress((void**)&Vh,   g_Vh);
    cudaGetSymbolAddress((void**)&S,    g_S);
    cudaGetSymbolAddress((void**)&H,    g_H);
    cudaGetSymbolAddress((void**)&deg,  g_deg);
    cudaGetSymbolAddress((void**)&off,  g_off);
    cudaGetSymbolAddress((void**)&cur,  g_cur);
    cudaGetSymbolAddress((void**)&srcs, g_srcs);
    cudaGetSymbolAddress((void**)&Wt,   g_Wt);

    // ---- side stream + events (created once on uncaptured correctness call) --
    static cudaStream_t s1 = 0;
    static cudaEvent_t evFork = 0, evJoin = 0, evG0 = 0, evJ1 = 0;
    if (s1 == 0) {
        cudaStreamCreateWithFlags(&s1, cudaStreamNonBlocking);
        cudaEventCreateWithFlags(&evFork, cudaEventDisableTiming);
        cudaEventCreateWithFlags(&evJoin, cudaEventDisableTiming);
        cudaEventCreateWithFlags(&evG0,   cudaEventDisableTiming);
        cudaEventCreateWithFlags(&evJ1,   cudaEventDisableTiming);
    }

    int tb = 256;
    dim3 tpb(32, 8);
    const int gy = (n + TM - 1) / TM;        // 79
    const int gyA = (gy + 1) / 2;            // 40 row-tiles
    const int gyB = gy - gyA;                // 39
    int na = gyA * TM; if (na > n) na = n;   // 5120
    int nb = n - na;                         // 4880

    // ---- fork: L1 transposes + CSR chain on side stream ----
    cudaEventRecord(evFork, 0);
    cudaStreamWaitEvent(s1, evFork, 0);
    {
        dim3 g1(QKV / 32, 128 / 32, 3);
        dim3 gs1(HID / 32, 128 / 32, 1);
        transpose3_kernel<<<g1, tpb, 0, s1>>>(Wq1, Wk1, Wv1,
                                              Wt + WT_Q1, Wt + WT_K1, Wt + WT_V1, 128, QKV);
        transpose3_kernel<<<gs1, tpb, 0, s1>>>(Ws1, Ws1, Ws1,
                                               Wt + WT_S1, Wt + WT_S1, Wt + WT_S1, 128, HID);
    }
    zero_int_kernel<<<(n + tb - 1) / tb, tb, 0, s1>>>(deg, n);
    count_deg_kernel<<<(e + tb - 1) / tb, tb, 0, s1>>>(ei + e, deg, e);
    scan_kernel<<<1, 1024, 0, s1>>>(deg, off, cur, n, e);
    scatter_kernel<<<(e + tb - 1) / tb, tb, 0, s1>>>(ei, cur, srcs, e);
    cudaEventRecord(evJoin, s1);   // CSR + L1 transposes done

    // ---- default: L0 transposes + GEMM0 ----
    {
        dim3 g0(QKV / 32, 256 / 32, 3);
        dim3 gs0(HID / 32, 256 / 32, 1);
        transpose3_kernel<<<g0, tpb>>>(Wq0, Wk0, Wv0,
                                       Wt + WT_Q0, Wt + WT_K0, Wt + WT_V0, 256, QKV);
        transpose3_kernel<<<gs0, tpb>>>(Ws0, Ws0, Ws0,
                                        Wt + WT_S0, Wt + WT_S0, Wt + WT_S0, 256, HID);
    }
    {
        dim3 g(QKV / TN, gy, 4);
        tf32_gemm4_kernel<<<g, 256>>>(x,
                                      Wt + WT_Q0, Wt + WT_K0, Wt + WT_V0, Wt + WT_S0,
                                      bq0, bk0, bv0, bs0,
                                      Q, Kh, Vh, S, n, 256, 0);
    }
    cudaEventRecord(evG0, 0);

    // ---- pipelined layer-0 attention / layer-1 GEMM (split by node halves) ---
    cudaStreamWaitEvent(0, evJoin, 0);       // default: CSR (+Wt L1) ready
    attn_fused_kernel<<<na, 128>>>(Q, Kh, Vh, S, off, srcs, H, 0);
    {
        dim3 gA(QKV / TN, gyA, 4);
        tf32_gemm4_kernel<<<gA, 256>>>(H,
                                       Wt + WT_Q1, Wt + WT_K1, Wt + WT_V1, Wt + WT_S1,
                                       bq1, bk1, bv1, bs1,
                                       Q, Kh, Vh, S, n, 128, 0);
    }
    // side stream: second half (CSR + transposes already ordered on s1)
    cudaStreamWaitEvent(s1, evG0, 0);
    attn_fused_kernel<<<nb, 128, 0, s1>>>(Q, Kh, Vh, S, off, srcs, H, na);
    {
        dim3 gB(QKV / TN, gyB, 4);
        tf32_gemm4_kernel<<<gB, 256, 0, s1>>>(H,
                                              Wt + WT_Q1, Wt + WT_K1, Wt + WT_V1, Wt + WT_S1,
                                              bq1, bk1, bv1, bs1,
                                              Q, Kh, Vh, S, n, 128, gyA);
    }
    cudaEventRecord(evJ1, s1);

    // ---- layer-1 attention (full) ----
    cudaStreamWaitEvent(0, evJ1, 0);
    attn_fused_kernel<<<n, 128>>>(Q, Kh, Vh, S, off, srcs, out, 0);
}